// round 13
// baseline (speedup 1.0000x reference)
#include <cuda_runtime.h>
#include <cuda_bf16.h>
#include <math.h>
#include <stdint.h>

#define BB   64
#define TT   128
#define DD   850
#define D2   1700
#define CIN  910
#define NCC  42
#define NNER 30
#define NPOS 30
#define SD   864          // padded k stride; pads stay zero
#define NTILE 54          // 16-col pair tiles
#define NKT  54           // k16 tiles
#define KQ   432          // k-pairs per row (SD/2)
#define WMATS 10          // 0..8 recurrent (W0bot, Ws[0..7]); 9 = W0top

// Scratch (device globals zero-initialized; pad regions never written)
__device__ float g_combined[TT * BB * CIN];
__device__ float g_xw0[TT * BB * D2];
__device__ float g_hiddens[TT * BB * DD];
__device__ float g_state[9][BB * SD];
__device__ float g_hprev[BB * SD];
__device__ int   g_tcnt[108];          // fold counters: mh*54 + tile
__device__ unsigned g_bar_cnt;
__device__ unsigned g_bar_gen;
// W fragments (2-way split): idx = ((wmat*NKT+kt)*NTILE+tile)*4 + ns, per lane.
__device__ __align__(256) uint4 g_Wf4[WMATS * NKT * NTILE * 4 * 32];
// Pre-split A (states 0..8, hprev=9): 2 bf16 terms, packed pairs over k.
__device__ __align__(256) uint32_t g_abf[10][2][BB * KQ];
// Pre-split x for xw0 mma: [term][r*KQ + d/2], r = t*BB+b
__device__ __align__(256) uint32_t g_xbf[2][TT * BB * KQ];

struct StepInfo { int wmat; int pred; int act; };
// act: 0 tanh, 1 relu, 2 sigmoid, 3 identity
__constant__ StepInfo c_steps[9] = {
    {0, -1, 0}, {1, 0, 2}, {2, 1, 1}, {3, 1, 1}, {4, 1, 3},
    {5, 2, 0}, {6, 5, 2}, {7, 3, 0}, {8, 5, 1},
};
// Levels: {s0},{s1},{s2,s3,s4},{s5,s7},{s6,s8}
__constant__ int c_nm[5]     = {1, 1, 3, 2, 2};
__constant__ int c_sid[5][3] = {{0,0,0},{1,1,1},{2,3,4},{5,7,7},{6,8,8}};

// Sense-reversing grid barrier (1 CTA/SM => co-resident).
__device__ __forceinline__ void grid_sync() {
    __syncthreads();
    if (threadIdx.x == 0) {
        __threadfence();
        volatile unsigned* vg = &g_bar_gen;
        unsigned gen = *vg;
        if (atomicAdd(&g_bar_cnt, 1u) == gridDim.x - 1) {
            g_bar_cnt = 0;
            __threadfence();
            atomicExch(&g_bar_gen, gen + 1u);
        } else {
            while (*vg == gen) { __nanosleep(32); }
        }
        __threadfence();
    }
    __syncthreads();
}

// 2-way bf16 split of a value pair -> 2 packed bf16x2 words (x low, y high).
__device__ __forceinline__ void split2_pair(float x, float y,
        uint32_t& u1, uint32_t& u2) {
    __nv_bfloat162 b1 = __floats2bfloat162_rn(x, y);
    float rx = x - __bfloat162float(__low2bfloat16(b1));
    float ry = y - __bfloat162float(__high2bfloat16(b1));
    __nv_bfloat162 b2 = __floats2bfloat162_rn(rx, ry);
    u1 = *(uint32_t*)&b1; u2 = *(uint32_t*)&b2;
}

__device__ __forceinline__ void mma_bf16(float* c, const uint32_t* a,
                                         uint32_t b0, uint32_t b1) {
    asm volatile(
        "mma.sync.aligned.m16n8k16.row.col.f32.bf16.bf16.f32 "
        "{%0,%1,%2,%3}, {%4,%5,%6,%7}, {%8,%9}, {%0,%1,%2,%3};"
        : "+f"(c[0]), "+f"(c[1]), "+f"(c[2]), "+f"(c[3])
        : "r"(a[0]), "r"(a[1]), "r"(a[2]), "r"(a[3]), "r"(b0), "r"(b1));
}

// ---------------------------------------------------------------------------
// K1: gather embeddings
// ---------------------------------------------------------------------------
__global__ void gather_kernel(const int* __restrict__ tokens,
                              const int* __restrict__ ner,
                              const int* __restrict__ pos,
                              const float* __restrict__ encW,
                              const float* __restrict__ nerW,
                              const float* __restrict__ posW) {
    int r = blockIdx.x;
    int b = r & (BB - 1);
    int t = r >> 6;
    int tok = tokens[b * TT + t];
    int nid = ner[b * TT + t];
    int pid = pos[b * TT + t];
    float* dst = g_combined + (size_t)r * CIN;
    for (int c = threadIdx.x; c < CIN; c += blockDim.x) {
        float v;
        if (c < DD)             v = encW[(size_t)tok * DD + c];
        else if (c < DD + NNER) v = nerW[nid * NNER + (c - DD)];
        else                    v = posW[pid * NPOS + (c - DD - NNER)];
        dst[c] = v;
    }
}

// ---------------------------------------------------------------------------
// K2: agg GEMM: x = combined @ aggW^T + aggb, epilogue writes SPLIT x only.
// ---------------------------------------------------------------------------
__global__ void gemm_agg_split(const float* __restrict__ A, const float* __restrict__ Bm,
                               const float* __restrict__ bias,
                               int M, int N, int K, int lda, int ldb) {
    __shared__ __align__(16) float As[16 * 64];
    __shared__ __align__(16) float Bs[16 * 64];
    int tid = threadIdx.x;
    int m0 = blockIdx.y * 64;
    int n0 = blockIdx.x * 64;
    int mi = tid & 15;
    int ni = tid >> 4;
    float acc[4][4] = {};

    for (int k0 = 0; k0 < K; k0 += 16) {
        __syncthreads();
        #pragma unroll
        for (int i = 0; i < 4; i++) {
            int e = tid + 256 * i;
            int m = e >> 4, k = e & 15;
            int kk = k0 + k;
            float v = 0.f;
            if (kk < K) v = A[(size_t)(m0 + m) * lda + kk];
            As[k * 64 + m] = v;
        }
        #pragma unroll
        for (int i = 0; i < 4; i++) {
            int e = tid + 256 * i;
            int n = e >> 4, k = e & 15;
            int kk = k0 + k, nn = n0 + n;
            float v = 0.f;
            if (kk < K && nn < N) v = Bm[(size_t)nn * ldb + kk];
            Bs[k * 64 + n] = v;
        }
        __syncthreads();
        #pragma unroll
        for (int k = 0; k < 16; k++) {
            float4 a4 = *(const float4*)(As + k * 64 + mi * 4);
            float4 b4 = *(const float4*)(Bs + k * 64 + ni * 4);
            acc[0][0] = fmaf(a4.x, b4.x, acc[0][0]);
            acc[0][1] = fmaf(a4.x, b4.y, acc[0][1]);
            acc[0][2] = fmaf(a4.x, b4.z, acc[0][2]);
            acc[0][3] = fmaf(a4.x, b4.w, acc[0][3]);
            acc[1][0] = fmaf(a4.y, b4.x, acc[1][0]);
            acc[1][1] = fmaf(a4.y, b4.y, acc[1][1]);
            acc[1][2] = fmaf(a4.y, b4.z, acc[1][2]);
            acc[1][3] = fmaf(a4.y, b4.w, acc[1][3]);
            acc[2][0] = fmaf(a4.z, b4.x, acc[2][0]);
            acc[2][1] = fmaf(a4.z, b4.y, acc[2][1]);
            acc[2][2] = fmaf(a4.z, b4.z, acc[2][2]);
            acc[2][3] = fmaf(a4.z, b4.w, acc[2][3]);
            acc[3][0] = fmaf(a4.w, b4.x, acc[3][0]);
            acc[3][1] = fmaf(a4.w, b4.y, acc[3][1]);
            acc[3][2] = fmaf(a4.w, b4.z, acc[3][2]);
            acc[3][3] = fmaf(a4.w, b4.w, acc[3][3]);
        }
    }
    #pragma unroll
    for (int r = 0; r < 4; r++) {
        int mm = m0 + mi * 4 + r;
        int nn0 = n0 + ni * 4;
        #pragma unroll
        for (int pr = 0; pr < 2; pr++) {
            int nn = nn0 + 2 * pr;
            if (nn < N) {   // N even => both pair elements valid
                float v0 = acc[r][2 * pr]     + bias[nn];
                float v1 = acc[r][2 * pr + 1] + bias[nn + 1];
                uint32_t u1, u2;
                split2_pair(v0, v1, u1, u2);
                size_t qi = (size_t)mm * KQ + (nn >> 1);
                g_xbf[0][qi] = u1;
                g_xbf[1][qi] = u2;
            }
        }
    }
}

// ---------------------------------------------------------------------------
// K3: pack weights into 2-term bf16 mma-fragment layout (10 matrices:
// 0 = W0 bottom (recurrent), 1..8 = Ws, 9 = W0 top (x path)).
// ---------------------------------------------------------------------------
__global__ void pack_w(const float* __restrict__ W0, const float* __restrict__ Ws) {
    int id = blockIdx.x;
    int pt = id % NTILE;
    int kt = (id / NTILE) % NKT;
    int mat = id / (NTILE * NKT);
    int ns = threadIdx.x >> 5;
    int lane = threadIdx.x & 31;
    const float* W = (mat == 0) ? (W0 + (size_t)DD * D2)
                   : (mat == 9) ? W0
                                : (Ws + (size_t)(mat - 1) * DD * D2);
    int half = ns >> 1;
    int col = pt * 16 + (ns & 1) * 8 + (lane >> 2);
    int gcol = (col < DD) ? (half ? DD + col : col) : -1;
    int k0 = kt * 16 + (lane & 3) * 2;
    float v[4];
    #pragma unroll
    for (int j = 0; j < 4; ++j) {
        int k = k0 + (j & 1) + (j >> 1) * 8;   // k0, k0+1, k0+8, k0+9
        v[j] = (gcol >= 0 && k < DD) ? W[(size_t)k * D2 + gcol] : 0.f;
    }
    uint32_t a1, a2, b1, b2;
    split2_pair(v[0], v[1], a1, a2);
    split2_pair(v[2], v[3], b1, b2);
    g_Wf4[((size_t)id * 4 + ns) * 32 + lane] = make_uint4(a1, b1, a2, b2);
}

// ---------------------------------------------------------------------------
// K4: xw0 = x @ W0top via fragment mma. grid = (54 tiles, 256 m-blocks).
// 8 warps = ng(2) x m16i(2) x kh(2); kh partials combined via smem.
// ---------------------------------------------------------------------------
__global__ __launch_bounds__(256)
void xw0_mma() {
    __shared__ float sm[2][32][33];
    const int tile = blockIdx.x;
    const int mb = blockIdx.y;
    const int tid = threadIdx.x;
    const int lane = tid & 31;
    const int w = tid >> 5;
    const int ng = w & 1;
    const int m16i = (w >> 1) & 1;
    const int kh = w >> 2;

    const int row0 = mb * 32 + m16i * 16 + (lane >> 2);
    const size_t ro = (size_t)row0 * KQ;
    const size_t r8 = ro + 8 * KQ;
    const int qk = lane & 3;

    const uint32_t* __restrict__ A1 = g_xbf[0];
    const uint32_t* __restrict__ A2 = g_xbf[1];

    float c0[4] = {0.f, 0.f, 0.f, 0.f};
    float c1[4] = {0.f, 0.f, 0.f, 0.f};

    const int ktb = kh * 27;
    #pragma unroll 3
    for (int kt = ktb; kt < ktb + 27; ++kt) {
        const int kq = kt * 8 + qk;
        uint32_t a1[4] = {A1[ro + kq], A1[r8 + kq], A1[ro + kq + 4], A1[r8 + kq + 4]};
        uint32_t a2[4] = {A2[ro + kq], A2[r8 + kq], A2[ro + kq + 4], A2[r8 + kq + 4]};
        size_t wb = ((size_t)((9 * NKT + kt) * NTILE + tile) * 4 + ng * 2) * 32 + lane;
        uint4 w40 = g_Wf4[wb];
        uint4 w41 = g_Wf4[wb + 32];
        mma_bf16(c0, a1, w40.x, w40.y);
        mma_bf16(c0, a1, w40.z, w40.w);
        mma_bf16(c0, a2, w40.x, w40.y);
        mma_bf16(c1, a1, w41.x, w41.y);
        mma_bf16(c1, a1, w41.z, w41.w);
        mma_bf16(c1, a2, w41.x, w41.y);
    }

    {
        const int rl = m16i * 16 + (lane >> 2);
        const int cb = ng * 16 + (lane & 3) * 2;
        sm[kh][rl][cb]         = c0[0];
        sm[kh][rl][cb + 1]     = c0[1];
        sm[kh][rl + 8][cb]     = c0[2];
        sm[kh][rl + 8][cb + 1] = c0[3];
        sm[kh][rl][cb + 8]         = c1[0];
        sm[kh][rl][cb + 9]         = c1[1];
        sm[kh][rl + 8][cb + 8]     = c1[2];
        sm[kh][rl + 8][cb + 9]     = c1[3];
    }
    __syncthreads();

    const int ml = tid >> 3;
    const int q = tid & 7;
    const int p0 = tile * 16 + 2 * q;
    const int row = mb * 32 + ml;
    if (p0 < DD) {
        float cc0 = sm[0][ml][2 * q]     + sm[1][ml][2 * q];
        float cc1 = sm[0][ml][2 * q + 1] + sm[1][ml][2 * q + 1];
        float hh0 = sm[0][ml][16 + 2 * q]     + sm[1][ml][16 + 2 * q];
        float hh1 = sm[0][ml][16 + 2 * q + 1] + sm[1][ml][16 + 2 * q + 1];
        float* xw = g_xw0 + (size_t)row * D2;
        *(float2*)&xw[p0]      = make_float2(cc0, cc1);
        *(float2*)&xw[DD + p0] = make_float2(hh0, hh1);
    }
}

// ---------------------------------------------------------------------------
// One recurrence job: C[32 rows x (16c+16h)] full-K, 3-pass 2-way-split mma.
// 8 warps = ng(2) x m16i(2) x khalf(2); khalf partials combined via smem.
// Level 4 jobs additionally fold next-step prep via per-(mh,tile) counter.
// ---------------------------------------------------------------------------
__device__ __forceinline__ void do_job(
    int t, int lvl, int j, float (*sm)[32][33], int* s_old)
{
    const int tile = j % NTILE;
    const int r = j / NTILE;
    const int mh = r & 1;
    const int mi = r >> 1;
    const int sid = c_sid[lvl][mi];
    const StepInfo si = c_steps[sid];
    const int asrc = (si.pred < 0) ? 9 : si.pred;
    const float* __restrict__ Afp = (si.pred < 0) ? g_hprev : g_state[si.pred];

    const int tid = threadIdx.x;
    const int lane = tid & 31;
    const int w = tid >> 5;
    const int ng = w & 1;
    const int m16i = (w >> 1) & 1;
    const int kh = w >> 2;

    const int r0g = mh * 32 + m16i * 16 + (lane >> 2);
    const int ro = r0g * KQ;
    const int r8 = ro + 8 * KQ;
    const int qk = lane & 3;

    const uint32_t* __restrict__ A1 = g_abf[asrc][0];
    const uint32_t* __restrict__ A2 = g_abf[asrc][1];

    float c0[4] = {0.f, 0.f, 0.f, 0.f};
    float c1[4] = {0.f, 0.f, 0.f, 0.f};

    const int ktb = kh * 27;
    #pragma unroll 3
    for (int kt = ktb; kt < ktb + 27; ++kt) {
        const int kq = kt * 8 + qk;
        uint32_t a1[4] = {A1[ro + kq], A1[r8 + kq], A1[ro + kq + 4], A1[r8 + kq + 4]};
        uint32_t a2[4] = {A2[ro + kq], A2[r8 + kq], A2[ro + kq + 4], A2[r8 + kq + 4]};
        size_t wb = ((size_t)((si.wmat * NKT + kt) * NTILE + tile) * 4 + ng * 2) * 32 + lane;
        uint4 w40 = g_Wf4[wb];
        uint4 w41 = g_Wf4[wb + 32];
        mma_bf16(c0, a1, w40.x, w40.y);   // x1*w1
        mma_bf16(c0, a1, w40.z, w40.w);   // x1*w2
        mma_bf16(c0, a2, w40.x, w40.y);   // x2*w1
        mma_bf16(c1, a1, w41.x, w41.y);
        mma_bf16(c1, a1, w41.z, w41.w);
        mma_bf16(c1, a2, w41.x, w41.y);
    }

    // store fragments to smem (khalf-partials)
    {
        const int rl = m16i * 16 + (lane >> 2);
        const int cb = ng * 16 + (lane & 3) * 2;
        sm[kh][rl][cb]         = c0[0];
        sm[kh][rl][cb + 1]     = c0[1];
        sm[kh][rl + 8][cb]     = c0[2];
        sm[kh][rl + 8][cb + 1] = c0[3];
        sm[kh][rl][cb + 8]         = c1[0];
        sm[kh][rl][cb + 9]         = c1[1];
        sm[kh][rl + 8][cb + 8]     = c1[2];
        sm[kh][rl + 8][cb + 9]     = c1[3];
    }
    __syncthreads();

    // epilogue: 256 threads = 32 rows x 8 col-pairs
    const int ml = tid >> 3;
    const int q = tid & 7;
    const int p0 = tile * 16 + 2 * q;
    const int m = mh * 32 + ml;
    if (p0 < DD) {
        float vv[2];
        #pragma unroll
        for (int e = 0; e < 2; ++e) {
            int cp = 2 * q + e;
            int p = p0 + e;
            float cc = sm[0][ml][cp] + sm[1][ml][cp];
            float hh = sm[0][ml][16 + cp] + sm[1][ml][16 + cp];
            if (si.pred < 0) {
                const float* xw = g_xw0 + ((size_t)t * BB + m) * D2;
                cc += __ldcs(xw + p);
                hh += __ldcs(xw + DD + p);
            }
            float sp = Afp[(size_t)m * SD + p];
            float g = 1.f / (1.f + expf(-cc));
            float av = (si.act == 0) ? tanhf(hh)
                     : (si.act == 1) ? fmaxf(hh, 0.f)
                     : (si.act == 2) ? 1.f / (1.f + expf(-hh)) : hh;
            vv[e] = sp + g * (av - sp);
        }
        *(float2*)&g_state[sid][(size_t)m * SD + p0] = make_float2(vv[0], vv[1]);
        uint32_t u1, u2;
        split2_pair(vv[0], vv[1], u1, u2);
        int qi = m * KQ + (p0 >> 1);
        g_abf[sid][0][qi] = u1;
        g_abf[sid][1][qi] = u2;
    }
    __syncthreads();   // smem reusable by next job

    // level-4 fold: when both mats (6,8) of this (mh,tile) block are done,
    // compute next-step hprev (+ hiddens[t]) for these rows/cols.
    if (lvl == 4) {
        __threadfence();
        __syncthreads();
        if (tid == 0) *s_old = atomicAdd(&g_tcnt[mh * 54 + tile], 1);
        __syncthreads();
        if (*s_old == 1) {
            __threadfence();
            if (p0 < DD) {
                float v0 = 0.f, v1 = 0.f;
                #pragma unroll
                for (int jj = 1; jj <= 8; ++jj) {
                    v0 += g_state[jj][(size_t)m * SD + p0];
                    v1 += g_state[jj][(size_t)m * SD + p0 + 1];
                }
                v0 *= 0.125f;
                v1 *= 0.125f;
                *(float2*)&g_hprev[(size_t)m * SD + p0] = make_float2(v0, v1);
                *(float2*)&g_hiddens[(size_t)t * BB * DD + (size_t)m * DD + p0]
                    = make_float2(v0, v1);
                uint32_t u1, u2;
                split2_pair(v0, v1, u1, u2);
                int qi = m * KQ + (p0 >> 1);
                g_abf[9][0][qi] = u1;
                g_abf[9][1][qi] = u2;
            }
            __syncthreads();
            if (tid == 0) g_tcnt[mh * 54 + tile] = 0;
        }
        __syncthreads();
    }
}

__global__ __launch_bounds__(256)
void recur_persist(const float* __restrict__ hidden) {
    __shared__ float sm[2][32][33];
    __shared__ int s_old;
    const int bid = blockIdx.x;
    const int G = gridDim.x;
    const int tid = threadIdx.x;

    // initial prep (t = 0): hprev = hidden, plus splits
    for (int i = bid * 256 + tid; i < BB * 425; i += G * 256) {
        int m = i / 425;
        int qd = i - m * 425;
        int d0 = 2 * qd;
        float v0 = hidden[m * DD + d0];
        float v1 = hidden[m * DD + d0 + 1];
        *(float2*)&g_hprev[(size_t)m * SD + d0] = make_float2(v0, v1);
        uint32_t u1, u2;
        split2_pair(v0, v1, u1, u2);
        int qi = m * KQ + qd;
        g_abf[9][0][qi] = u1;
        g_abf[9][1][qi] = u2;
    }
    grid_sync();

    for (int t = 0; t < TT; ++t) {
        #pragma unroll
        for (int lvl = 0; lvl < 5; ++lvl) {
            const int jobs = c_nm[lvl] * 108;
            for (int j = bid; j < jobs; j += G)
                do_job(t, lvl, j, sm, &s_old);
            grid_sync();
        }
    }
}

// ---------------------------------------------------------------------------
// K5: mean over T, decoder, log_softmax, new_hidden.
// ---------------------------------------------------------------------------
__global__ void final_kernel(const float* __restrict__ masks,
                             const float* __restrict__ decW,
                             const float* __restrict__ decb,
                             float* __restrict__ out) {
    int b = blockIdx.x;
    int tid = threadIdx.x;
    __shared__ float sout[DD];
    __shared__ float lg[NCC];
    __shared__ float lse;

    float mask_last = masks[b * TT + TT - 1];
    for (int d = tid; d < DD; d += blockDim.x) {
        float ms = 0.f;
        #pragma unroll
        for (int j = 1; j <= 8; j++) ms += g_state[j][b * SD + d];
        ms *= 0.125f;
        float last_raw = ms * mask_last;
        float acc = last_raw;
        for (int t = 0; t < TT - 1; t++)
            acc += g_hiddens[(size_t)t * BB * DD + b * DD + d] * masks[b * TT + t];
        sout[d] = acc * (1.f / TT);
        out[NCC * BB + b * DD + d] = last_raw;
    }
    __syncthreads();

    for (int c = tid; c < NCC; c += blockDim.x) {
        float acc = decb[c];
        const float* w = decW + (size_t)c * DD;
        for (int d = 0; d < DD; d++) acc = fmaf(sout[d], w[d], acc);
        lg[c] = acc;
    }
    __syncthreads();

    if (tid == 0) {
        float mx = lg[0];
        for (int c = 1; c < NCC; c++) mx = fmaxf(mx, lg[c]);
        float s = 0.f;
        for (int c = 0; c < NCC; c++) s += expf(lg[c] - mx);
        lse = mx + logf(s);
    }
    __syncthreads();

    for (int c = tid; c < NCC; c += blockDim.x)
        out[b * NCC + c] = lg[c] - lse;
}

// ---------------------------------------------------------------------------
// Host launcher
// ---------------------------------------------------------------------------
extern "C" void kernel_launch(void* const* d_in, const int* in_sizes, int n_in,
                              void* d_out, int out_size) {
    const int*   tokens = (const int*)  d_in[0];
    const float* masks  = (const float*)d_in[1];
    const int*   pos    = (const int*)  d_in[2];
    const int*   ner    = (const int*)  d_in[3];
    const float* hidden = (const float*)d_in[4];
    const float* encW   = (const float*)d_in[5];
    const float* nerW   = (const float*)d_in[6];
    const float* posW   = (const float*)d_in[7];
    const float* aggW   = (const float*)d_in[8];
    const float* aggb   = (const float*)d_in[9];
    const float* W0     = (const float*)d_in[10];
    const float* Ws     = (const float*)d_in[11];
    const float* decW   = (const float*)d_in[12];
    const float* decb   = (const float*)d_in[13];
    float* out = (float*)d_out;

    static int s_grid = 0;
    if (s_grid == 0) {
        int dev = 0;
        cudaGetDevice(&dev);
        cudaDeviceProp prop;
        cudaGetDeviceProperties(&prop, dev);
        s_grid = prop.multiProcessorCount;   // 1 CTA/SM: co-resident, cheap barrier
    }

    float* p_combined;
    cudaGetSymbolAddress((void**)&p_combined, g_combined);

    // 1) gather embeddings + pack weights (independent)
    gather_kernel<<<TT * BB, 128>>>(tokens, ner, pos, encW, nerW, posW);
    pack_w<<<WMATS * NKT * NTILE, 128>>>(W0, Ws);

    // 2) agg linear -> pre-split x   [8192, 850]
    {
        dim3 g((DD + 63) / 64, (TT * BB) / 64);
        gemm_agg_split<<<g, 256>>>(p_combined, aggW, aggb,
                                   TT * BB, DD, CIN, CIN, CIN);
    }
    // 3) xw0 = x @ W0top via fragment mma   [8192, 1700]
    xw0_mma<<<dim3(NTILE, (TT * BB) / 32), 256>>>();

    // 4) whole recurrence in ONE persistent kernel
    recur_persist<<<s_grid, 256>>>(hidden);

    // 5) mean over T, decoder, log_softmax, new_hidden
    final_kernel<<<BB, 256>>>(masks, decW, decb, out);
}

// round 14
// speedup vs baseline: 1.2638x; 1.2638x over previous
#include <cuda_runtime.h>
#include <cuda_bf16.h>
#include <math.h>
#include <stdint.h>

#define BB   64
#define TT   128
#define DD   850
#define D2   1700
#define CIN  910
#define NCC  42
#define NNER 30
#define NPOS 30
#define SD   864          // padded k stride; pads stay zero
#define NTILE 54          // 16-col pair tiles
#define NKT  54           // k16 tiles
#define KQ   432          // k-pairs per row (SD/2)
#define WMATS 10          // 0..8 recurrent (W0bot, Ws[0..7]); 9 = W0top

// Scratch (device globals zero-initialized; pad regions never written)
__device__ float g_combined[TT * BB * CIN];
__device__ float g_xw0[TT * BB * D2];
__device__ float g_hiddens[TT * BB * DD];
__device__ float g_state[9][BB * SD];
__device__ float g_hprev[BB * SD];
__device__ int   g_tcnt[108];          // fold counters: mh*54 + tile
__device__ unsigned g_bar_cnt;
__device__ unsigned g_bar_gen;
// W fragments (2-way split): idx = ((wmat*NKT+kt)*NTILE+tile)*4 + ns, per lane.
__device__ __align__(256) uint4 g_Wf4[WMATS * NKT * NTILE * 4 * 32];
// Pre-split A (states 0..8, hprev=9): 2 bf16 terms, packed pairs over k.
__device__ __align__(256) uint32_t g_abf[10][2][BB * KQ];
// Pre-split x for xw0 mma: [term][r*KQ + d/2], r = t*BB+b
__device__ __align__(256) uint32_t g_xbf[2][TT * BB * KQ];

struct StepInfo { int wmat; int pred; int act; };
// act: 0 tanh, 1 relu, 2 sigmoid, 3 identity
__constant__ StepInfo c_steps[9] = {
    {0, -1, 0}, {1, 0, 2}, {2, 1, 1}, {3, 1, 1}, {4, 1, 3},
    {5, 2, 0}, {6, 5, 2}, {7, 3, 0}, {8, 5, 1},
};
// Levels: {s0},{s1},{s2,s3,s4},{s5,s7},{s6,s8}
__constant__ int c_nm[5]     = {1, 1, 3, 2, 2};
__constant__ int c_sid[5][3] = {{0,0,0},{1,1,1},{2,3,4},{5,7,7},{6,8,8}};

// Sense-reversing grid barrier (1 CTA/SM => co-resident).
__device__ __forceinline__ void grid_sync() {
    __syncthreads();
    if (threadIdx.x == 0) {
        __threadfence();
        volatile unsigned* vg = &g_bar_gen;
        unsigned gen = *vg;
        if (atomicAdd(&g_bar_cnt, 1u) == gridDim.x - 1) {
            g_bar_cnt = 0;
            __threadfence();
            atomicExch(&g_bar_gen, gen + 1u);
        } else {
            while (*vg == gen) { __nanosleep(64); }
        }
        __threadfence();
    }
    __syncthreads();
}

// 2-way bf16 split of a value pair -> 2 packed bf16x2 words (x low, y high).
__device__ __forceinline__ void split2_pair(float x, float y,
        uint32_t& u1, uint32_t& u2) {
    __nv_bfloat162 b1 = __floats2bfloat162_rn(x, y);
    float rx = x - __bfloat162float(__low2bfloat16(b1));
    float ry = y - __bfloat162float(__high2bfloat16(b1));
    __nv_bfloat162 b2 = __floats2bfloat162_rn(rx, ry);
    u1 = *(uint32_t*)&b1; u2 = *(uint32_t*)&b2;
}

__device__ __forceinline__ void mma_bf16(float* c, const uint32_t* a,
                                         uint32_t b0, uint32_t b1) {
    asm volatile(
        "mma.sync.aligned.m16n8k16.row.col.f32.bf16.bf16.f32 "
        "{%0,%1,%2,%3}, {%4,%5,%6,%7}, {%8,%9}, {%0,%1,%2,%3};"
        : "+f"(c[0]), "+f"(c[1]), "+f"(c[2]), "+f"(c[3])
        : "r"(a[0]), "r"(a[1]), "r"(a[2]), "r"(a[3]), "r"(b0), "r"(b1));
}

// ---------------------------------------------------------------------------
// K1: gather embeddings
// ---------------------------------------------------------------------------
__global__ void gather_kernel(const int* __restrict__ tokens,
                              const int* __restrict__ ner,
                              const int* __restrict__ pos,
                              const float* __restrict__ encW,
                              const float* __restrict__ nerW,
                              const float* __restrict__ posW) {
    int r = blockIdx.x;
    int b = r & (BB - 1);
    int t = r >> 6;
    int tok = tokens[b * TT + t];
    int nid = ner[b * TT + t];
    int pid = pos[b * TT + t];
    float* dst = g_combined + (size_t)r * CIN;
    for (int c = threadIdx.x; c < CIN; c += blockDim.x) {
        float v;
        if (c < DD)             v = encW[(size_t)tok * DD + c];
        else if (c < DD + NNER) v = nerW[nid * NNER + (c - DD)];
        else                    v = posW[pid * NPOS + (c - DD - NNER)];
        dst[c] = v;
    }
}

// ---------------------------------------------------------------------------
// K2: agg GEMM: x = combined @ aggW^T + aggb, epilogue writes SPLIT x only.
// ---------------------------------------------------------------------------
__global__ void gemm_agg_split(const float* __restrict__ A, const float* __restrict__ Bm,
                               const float* __restrict__ bias,
                               int M, int N, int K, int lda, int ldb) {
    __shared__ __align__(16) float As[16 * 64];
    __shared__ __align__(16) float Bs[16 * 64];
    int tid = threadIdx.x;
    int m0 = blockIdx.y * 64;
    int n0 = blockIdx.x * 64;
    int mi = tid & 15;
    int ni = tid >> 4;
    float acc[4][4] = {};

    for (int k0 = 0; k0 < K; k0 += 16) {
        __syncthreads();
        #pragma unroll
        for (int i = 0; i < 4; i++) {
            int e = tid + 256 * i;
            int m = e >> 4, k = e & 15;
            int kk = k0 + k;
            float v = 0.f;
            if (kk < K) v = A[(size_t)(m0 + m) * lda + kk];
            As[k * 64 + m] = v;
        }
        #pragma unroll
        for (int i = 0; i < 4; i++) {
            int e = tid + 256 * i;
            int n = e >> 4, k = e & 15;
            int kk = k0 + k, nn = n0 + n;
            float v = 0.f;
            if (kk < K && nn < N) v = Bm[(size_t)nn * ldb + kk];
            Bs[k * 64 + n] = v;
        }
        __syncthreads();
        #pragma unroll
        for (int k = 0; k < 16; k++) {
            float4 a4 = *(const float4*)(As + k * 64 + mi * 4);
            float4 b4 = *(const float4*)(Bs + k * 64 + ni * 4);
            acc[0][0] = fmaf(a4.x, b4.x, acc[0][0]);
            acc[0][1] = fmaf(a4.x, b4.y, acc[0][1]);
            acc[0][2] = fmaf(a4.x, b4.z, acc[0][2]);
            acc[0][3] = fmaf(a4.x, b4.w, acc[0][3]);
            acc[1][0] = fmaf(a4.y, b4.x, acc[1][0]);
            acc[1][1] = fmaf(a4.y, b4.y, acc[1][1]);
            acc[1][2] = fmaf(a4.y, b4.z, acc[1][2]);
            acc[1][3] = fmaf(a4.y, b4.w, acc[1][3]);
            acc[2][0] = fmaf(a4.z, b4.x, acc[2][0]);
            acc[2][1] = fmaf(a4.z, b4.y, acc[2][1]);
            acc[2][2] = fmaf(a4.z, b4.z, acc[2][2]);
            acc[2][3] = fmaf(a4.z, b4.w, acc[2][3]);
            acc[3][0] = fmaf(a4.w, b4.x, acc[3][0]);
            acc[3][1] = fmaf(a4.w, b4.y, acc[3][1]);
            acc[3][2] = fmaf(a4.w, b4.z, acc[3][2]);
            acc[3][3] = fmaf(a4.w, b4.w, acc[3][3]);
        }
    }
    #pragma unroll
    for (int r = 0; r < 4; r++) {
        int mm = m0 + mi * 4 + r;
        int nn0 = n0 + ni * 4;
        #pragma unroll
        for (int pr = 0; pr < 2; pr++) {
            int nn = nn0 + 2 * pr;
            if (nn < N) {   // N even => both pair elements valid
                float v0 = acc[r][2 * pr]     + bias[nn];
                float v1 = acc[r][2 * pr + 1] + bias[nn + 1];
                uint32_t u1, u2;
                split2_pair(v0, v1, u1, u2);
                size_t qi = (size_t)mm * KQ + (nn >> 1);
                g_xbf[0][qi] = u1;
                g_xbf[1][qi] = u2;
            }
        }
    }
}

// ---------------------------------------------------------------------------
// K3: pack weights into 2-term bf16 mma-fragment layout (10 matrices:
// 0 = W0 bottom (recurrent), 1..8 = Ws, 9 = W0 top (x path)).
// ---------------------------------------------------------------------------
__global__ void pack_w(const float* __restrict__ W0, const float* __restrict__ Ws) {
    int id = blockIdx.x;
    int pt = id % NTILE;
    int kt = (id / NTILE) % NKT;
    int mat = id / (NTILE * NKT);
    int ns = threadIdx.x >> 5;
    int lane = threadIdx.x & 31;
    const float* W = (mat == 0) ? (W0 + (size_t)DD * D2)
                   : (mat == 9) ? W0
                                : (Ws + (size_t)(mat - 1) * DD * D2);
    int half = ns >> 1;
    int col = pt * 16 + (ns & 1) * 8 + (lane >> 2);
    int gcol = (col < DD) ? (half ? DD + col : col) : -1;
    int k0 = kt * 16 + (lane & 3) * 2;
    float v[4];
    #pragma unroll
    for (int j = 0; j < 4; ++j) {
        int k = k0 + (j & 1) + (j >> 1) * 8;   // k0, k0+1, k0+8, k0+9
        v[j] = (gcol >= 0 && k < DD) ? W[(size_t)k * D2 + gcol] : 0.f;
    }
    uint32_t a1, a2, b1, b2;
    split2_pair(v[0], v[1], a1, a2);
    split2_pair(v[2], v[3], b1, b2);
    g_Wf4[((size_t)id * 4 + ns) * 32 + lane] = make_uint4(a1, b1, a2, b2);
}

// ---------------------------------------------------------------------------
// K4: xw0 = x @ W0top via fragment mma. grid = (54 tiles, 256 m-blocks).
// 8 warps = ng(2) x m16i(2) x kh(2); kh partials combined via smem.
// ---------------------------------------------------------------------------
__global__ __launch_bounds__(256)
void xw0_mma() {
    __shared__ float sm[2][32][33];
    const int tile = blockIdx.x;
    const int mb = blockIdx.y;
    const int tid = threadIdx.x;
    const int lane = tid & 31;
    const int w = tid >> 5;
    const int ng = w & 1;
    const int m16i = (w >> 1) & 1;
    const int kh = w >> 2;

    const int row0 = mb * 32 + m16i * 16 + (lane >> 2);
    const size_t ro = (size_t)row0 * KQ;
    const size_t r8 = ro + 8 * KQ;
    const int qk = lane & 3;

    const uint32_t* __restrict__ A1 = g_xbf[0];
    const uint32_t* __restrict__ A2 = g_xbf[1];

    float c0[4] = {0.f, 0.f, 0.f, 0.f};
    float c1[4] = {0.f, 0.f, 0.f, 0.f};

    const int ktb = kh * 27;
    #pragma unroll 3
    for (int kt = ktb; kt < ktb + 27; ++kt) {
        const int kq = kt * 8 + qk;
        uint32_t a1[4] = {A1[ro + kq], A1[r8 + kq], A1[ro + kq + 4], A1[r8 + kq + 4]};
        uint32_t a2[4] = {A2[ro + kq], A2[r8 + kq], A2[ro + kq + 4], A2[r8 + kq + 4]};
        size_t wb = ((size_t)((9 * NKT + kt) * NTILE + tile) * 4 + ng * 2) * 32 + lane;
        uint4 w40 = g_Wf4[wb];
        uint4 w41 = g_Wf4[wb + 32];
        mma_bf16(c0, a1, w40.x, w40.y);
        mma_bf16(c0, a1, w40.z, w40.w);
        mma_bf16(c0, a2, w40.x, w40.y);
        mma_bf16(c1, a1, w41.x, w41.y);
        mma_bf16(c1, a1, w41.z, w41.w);
        mma_bf16(c1, a2, w41.x, w41.y);
    }

    {
        const int rl = m16i * 16 + (lane >> 2);
        const int cb = ng * 16 + (lane & 3) * 2;
        sm[kh][rl][cb]         = c0[0];
        sm[kh][rl][cb + 1]     = c0[1];
        sm[kh][rl + 8][cb]     = c0[2];
        sm[kh][rl + 8][cb + 1] = c0[3];
        sm[kh][rl][cb + 8]         = c1[0];
        sm[kh][rl][cb + 9]         = c1[1];
        sm[kh][rl + 8][cb + 8]     = c1[2];
        sm[kh][rl + 8][cb + 9]     = c1[3];
    }
    __syncthreads();

    const int ml = tid >> 3;
    const int q = tid & 7;
    const int p0 = tile * 16 + 2 * q;
    const int row = mb * 32 + ml;
    if (p0 < DD) {
        float cc0 = sm[0][ml][2 * q]     + sm[1][ml][2 * q];
        float cc1 = sm[0][ml][2 * q + 1] + sm[1][ml][2 * q + 1];
        float hh0 = sm[0][ml][16 + 2 * q]     + sm[1][ml][16 + 2 * q];
        float hh1 = sm[0][ml][16 + 2 * q + 1] + sm[1][ml][16 + 2 * q + 1];
        float* xw = g_xw0 + (size_t)row * D2;
        __stcs((float2*)&xw[p0],      make_float2(cc0, cc1));
        __stcs((float2*)&xw[DD + p0], make_float2(hh0, hh1));
    }
}

// ---------------------------------------------------------------------------
// One recurrence job: C[32 rows x (16c+16h)] full-K, 3-pass 2-way-split mma.
// 8 warps = ng(2) x m16i(2) x khalf(2); khalf partials combined via smem.
// Level 4 jobs additionally fold next-step prep via per-(mh,tile) counter.
// ---------------------------------------------------------------------------
__device__ __forceinline__ void do_job(
    int t, int lvl, int j, float (*sm)[32][33], int* s_old)
{
    const int tile = j % NTILE;
    const int r = j / NTILE;
    const int mh = r & 1;
    const int mi = r >> 1;
    const int sid = c_sid[lvl][mi];
    const StepInfo si = c_steps[sid];
    const int asrc = (si.pred < 0) ? 9 : si.pred;
    const float* __restrict__ Afp = (si.pred < 0) ? g_hprev : g_state[si.pred];

    const int tid = threadIdx.x;
    const int lane = tid & 31;
    const int w = tid >> 5;
    const int ng = w & 1;
    const int m16i = (w >> 1) & 1;
    const int kh = w >> 2;

    const int r0g = mh * 32 + m16i * 16 + (lane >> 2);
    const int ro = r0g * KQ;
    const int r8 = ro + 8 * KQ;
    const int qk = lane & 3;

    const uint32_t* __restrict__ A1 = g_abf[asrc][0];
    const uint32_t* __restrict__ A2 = g_abf[asrc][1];

    float c0[4] = {0.f, 0.f, 0.f, 0.f};
    float c1[4] = {0.f, 0.f, 0.f, 0.f};

    const int ktb = kh * 27;
    #pragma unroll 3
    for (int kt = ktb; kt < ktb + 27; ++kt) {
        const int kq = kt * 8 + qk;
        uint32_t a1[4] = {A1[ro + kq], A1[r8 + kq], A1[ro + kq + 4], A1[r8 + kq + 4]};
        uint32_t a2[4] = {A2[ro + kq], A2[r8 + kq], A2[ro + kq + 4], A2[r8 + kq + 4]};
        size_t wb = ((size_t)((si.wmat * NKT + kt) * NTILE + tile) * 4 + ng * 2) * 32 + lane;
        uint4 w40 = g_Wf4[wb];
        uint4 w41 = g_Wf4[wb + 32];
        mma_bf16(c0, a1, w40.x, w40.y);   // x1*w1
        mma_bf16(c0, a1, w40.z, w40.w);   // x1*w2
        mma_bf16(c0, a2, w40.x, w40.y);   // x2*w1
        mma_bf16(c1, a1, w41.x, w41.y);
        mma_bf16(c1, a1, w41.z, w41.w);
        mma_bf16(c1, a2, w41.x, w41.y);
    }

    // store fragments to smem (khalf-partials)
    {
        const int rl = m16i * 16 + (lane >> 2);
        const int cb = ng * 16 + (lane & 3) * 2;
        sm[kh][rl][cb]         = c0[0];
        sm[kh][rl][cb + 1]     = c0[1];
        sm[kh][rl + 8][cb]     = c0[2];
        sm[kh][rl + 8][cb + 1] = c0[3];
        sm[kh][rl][cb + 8]         = c1[0];
        sm[kh][rl][cb + 9]         = c1[1];
        sm[kh][rl + 8][cb + 8]     = c1[2];
        sm[kh][rl + 8][cb + 9]     = c1[3];
    }
    __syncthreads();

    // epilogue: 256 threads = 32 rows x 8 col-pairs
    const int ml = tid >> 3;
    const int q = tid & 7;
    const int p0 = tile * 16 + 2 * q;
    const int m = mh * 32 + ml;
    if (p0 < DD) {
        float vv[2];
        #pragma unroll
        for (int e = 0; e < 2; ++e) {
            int cp = 2 * q + e;
            int p = p0 + e;
            float cc = sm[0][ml][cp] + sm[1][ml][cp];
            float hh = sm[0][ml][16 + cp] + sm[1][ml][16 + cp];
            if (si.pred < 0) {
                const float* xw = g_xw0 + ((size_t)t * BB + m) * D2;
                cc += __ldcs(xw + p);
                hh += __ldcs(xw + DD + p);
            }
            float sp = Afp[(size_t)m * SD + p];
            float g = 1.f / (1.f + expf(-cc));
            float av = (si.act == 0) ? tanhf(hh)
                     : (si.act == 1) ? fmaxf(hh, 0.f)
                     : (si.act == 2) ? 1.f / (1.f + expf(-hh)) : hh;
            vv[e] = sp + g * (av - sp);
        }
        *(float2*)&g_state[sid][(size_t)m * SD + p0] = make_float2(vv[0], vv[1]);
        uint32_t u1, u2;
        split2_pair(vv[0], vv[1], u1, u2);
        int qi = m * KQ + (p0 >> 1);
        g_abf[sid][0][qi] = u1;
        g_abf[sid][1][qi] = u2;
    }
    __syncthreads();   // smem reusable by next job

    // level-4 fold: when both mats (6,8) of this (mh,tile) block are done,
    // compute next-step hprev (+ hiddens[t]) for these rows/cols.
    if (lvl == 4) {
        __threadfence();
        __syncthreads();
        if (tid == 0) *s_old = atomicAdd(&g_tcnt[mh * 54 + tile], 1);
        __syncthreads();
        if (*s_old == 1) {
            __threadfence();
            if (p0 < DD) {
                float v0 = 0.f, v1 = 0.f;
                #pragma unroll
                for (int jj = 1; jj <= 8; ++jj) {
                    v0 += g_state[jj][(size_t)m * SD + p0];
                    v1 += g_state[jj][(size_t)m * SD + p0 + 1];
                }
                v0 *= 0.125f;
                v1 *= 0.125f;
                *(float2*)&g_hprev[(size_t)m * SD + p0] = make_float2(v0, v1);
                *(float2*)&g_hiddens[(size_t)t * BB * DD + (size_t)m * DD + p0]
                    = make_float2(v0, v1);
                uint32_t u1, u2;
                split2_pair(v0, v1, u1, u2);
                int qi = m * KQ + (p0 >> 1);
                g_abf[9][0][qi] = u1;
                g_abf[9][1][qi] = u2;
            }
            __syncthreads();
            if (tid == 0) g_tcnt[mh * 54 + tile] = 0;
        }
        __syncthreads();
    }
}

__global__ __launch_bounds__(256, 2)
void recur_persist(const float* __restrict__ hidden) {
    __shared__ float sm[2][32][33];
    __shared__ int s_old;
    const int bid = blockIdx.x;
    const int G = gridDim.x;
    const int tid = threadIdx.x;

    // initial prep (t = 0): hprev = hidden, plus splits
    for (int i = bid * 256 + tid; i < BB * 425; i += G * 256) {
        int m = i / 425;
        int qd = i - m * 425;
        int d0 = 2 * qd;
        float v0 = hidden[m * DD + d0];
        float v1 = hidden[m * DD + d0 + 1];
        *(float2*)&g_hprev[(size_t)m * SD + d0] = make_float2(v0, v1);
        uint32_t u1, u2;
        split2_pair(v0, v1, u1, u2);
        int qi = m * KQ + qd;
        g_abf[9][0][qi] = u1;
        g_abf[9][1][qi] = u2;
    }
    grid_sync();

    for (int t = 0; t < TT; ++t) {
        #pragma unroll
        for (int lvl = 0; lvl < 5; ++lvl) {
            const int jobs = c_nm[lvl] * 108;
            for (int j = bid; j < jobs; j += G)
                do_job(t, lvl, j, sm, &s_old);
            grid_sync();
        }
    }
}

// ---------------------------------------------------------------------------
// K5: mean over T, decoder, log_softmax, new_hidden.
// ---------------------------------------------------------------------------
__global__ void final_kernel(const float* __restrict__ masks,
                             const float* __restrict__ decW,
                             const float* __restrict__ decb,
                             float* __restrict__ out) {
    int b = blockIdx.x;
    int tid = threadIdx.x;
    __shared__ float sout[DD];
    __shared__ float lg[NCC];
    __shared__ float lse;

    float mask_last = masks[b * TT + TT - 1];
    for (int d = tid; d < DD; d += blockDim.x) {
        float ms = 0.f;
        #pragma unroll
        for (int j = 1; j <= 8; j++) ms += g_state[j][b * SD + d];
        ms *= 0.125f;
        float last_raw = ms * mask_last;
        float acc = last_raw;
        for (int t = 0; t < TT - 1; t++)
            acc += g_hiddens[(size_t)t * BB * DD + b * DD + d] * masks[b * TT + t];
        sout[d] = acc * (1.f / TT);
        out[NCC * BB + b * DD + d] = last_raw;
    }
    __syncthreads();

    for (int c = tid; c < NCC; c += blockDim.x) {
        float acc = decb[c];
        const float* w = decW + (size_t)c * DD;
        for (int d = 0; d < DD; d++) acc = fmaf(sout[d], w[d], acc);
        lg[c] = acc;
    }
    __syncthreads();

    if (tid == 0) {
        float mx = lg[0];
        for (int c = 1; c < NCC; c++) mx = fmaxf(mx, lg[c]);
        float s = 0.f;
        for (int c = 0; c < NCC; c++) s += expf(lg[c] - mx);
        lse = mx + logf(s);
    }
    __syncthreads();

    for (int c = tid; c < NCC; c += blockDim.x)
        out[b * NCC + c] = lg[c] - lse;
}

// ---------------------------------------------------------------------------
// Host launcher
// ---------------------------------------------------------------------------
extern "C" void kernel_launch(void* const* d_in, const int* in_sizes, int n_in,
                              void* d_out, int out_size) {
    const int*   tokens = (const int*)  d_in[0];
    const float* masks  = (const float*)d_in[1];
    const int*   pos    = (const int*)  d_in[2];
    const int*   ner    = (const int*)  d_in[3];
    const float* hidden = (const float*)d_in[4];
    const float* encW   = (const float*)d_in[5];
    const float* nerW   = (const float*)d_in[6];
    const float* posW   = (const float*)d_in[7];
    const float* aggW   = (const float*)d_in[8];
    const float* aggb   = (const float*)d_in[9];
    const float* W0     = (const float*)d_in[10];
    const float* Ws     = (const float*)d_in[11];
    const float* decW   = (const float*)d_in[12];
    const float* decb   = (const float*)d_in[13];
    float* out = (float*)d_out;

    static int s_grid = 0;
    if (s_grid == 0) {
        int dev = 0;
        cudaGetDevice(&dev);
        cudaDeviceProp prop;
        cudaGetDeviceProperties(&prop, dev);
        s_grid = prop.multiProcessorCount;   // 1 CTA/SM: co-resident, cheap barrier
    }

    float* p_combined;
    cudaGetSymbolAddress((void**)&p_combined, g_combined);

    // 1) gather embeddings + pack weights (independent)
    gather_kernel<<<TT * BB, 128>>>(tokens, ner, pos, encW, nerW, posW);
    pack_w<<<WMATS * NKT * NTILE, 128>>>(W0, Ws);

    // 2) agg linear -> pre-split x   [8192, 850]
    {
        dim3 g((DD + 63) / 64, (TT * BB) / 64);
        gemm_agg_split<<<g, 256>>>(p_combined, aggW, aggb,
                                   TT * BB, DD, CIN, CIN, CIN);
    }
    // 3) xw0 = x @ W0top via fragment mma   [8192, 1700]
    xw0_mma<<<dim3(NTILE, (TT * BB) / 32), 256>>>();

    // 4) whole recurrence in ONE persistent kernel
    recur_persist<<<s_grid, 256>>>(hidden);

    // 5) mean over T, decoder, log_softmax, new_hidden
    final_kernel<<<BB, 256>>>(masks, decW, decb, out);
}

// round 15
// speedup vs baseline: 1.8190x; 1.4393x over previous
#include <cuda_runtime.h>
#include <cuda_bf16.h>
#include <math.h>
#include <stdint.h>

#define BB   64
#define TT   128
#define DD   850
#define D2   1700
#define CIN  910
#define NCC  42
#define NNER 30
#define NPOS 30
#define SD   864          // padded k stride; pads stay zero
#define NTILE 54          // 16-col pair tiles
#define NKT  54           // k16 tiles
#define WMATS 10          // 0..8 recurrent (W0bot, Ws[0..7]); 9 = W0top
#define XSTRIPS (TT * BB / 16)   // 512 row-strips of x

// Scratch (device globals zero-initialized; pad regions never written)
__device__ float g_combined[TT * BB * CIN];
__device__ float g_xw0[TT * BB * D2];
__device__ float g_hiddens[TT * BB * DD];
__device__ float g_state[9][BB * SD];
__device__ float g_hprev[BB * SD];
__device__ int   g_tcnt[108];          // fold counters: mh*54 + tile
__device__ unsigned g_bar_cnt;
__device__ unsigned g_bar_gen;
// W fragments (2-way split): idx = ((wmat*NKT+kt)*NTILE+tile)*4 + ns, per lane.
__device__ __align__(256) uint4 g_Wf4[WMATS * NKT * NTILE * 4 * 32];
// A fragments (states 0..8, hprev=9), mma-A layout:
// uint4 per lane = {j0,j1,j2,j3}; idx = ((src*4+strip)*NKT+kt)*2 + term, x32 lanes
__device__ __align__(256) uint4 g_af4[10 * 4 * NKT * 2 * 32];
// x fragments for xw0 mma: idx = ((strip*NKT+kt)*2 + term) x32 lanes
__device__ __align__(256) uint4 g_xf4[(size_t)XSTRIPS * NKT * 2 * 32];

struct StepInfo { int wmat; int pred; int act; };
// act: 0 tanh, 1 relu, 2 sigmoid, 3 identity
__constant__ StepInfo c_steps[9] = {
    {0, -1, 0}, {1, 0, 2}, {2, 1, 1}, {3, 1, 1}, {4, 1, 3},
    {5, 2, 0}, {6, 5, 2}, {7, 3, 0}, {8, 5, 1},
};
// Levels: {s0},{s1},{s2,s3,s4},{s5,s7},{s6,s8}
__constant__ int c_nm[5]     = {1, 1, 3, 2, 2};
__constant__ int c_sid[5][3] = {{0,0,0},{1,1,1},{2,3,4},{5,7,7},{6,8,8}};

// Sense-reversing grid barrier (1 CTA/SM => co-resident).
__device__ __forceinline__ void grid_sync() {
    __syncthreads();
    if (threadIdx.x == 0) {
        __threadfence();
        volatile unsigned* vg = &g_bar_gen;
        unsigned gen = *vg;
        if (atomicAdd(&g_bar_cnt, 1u) == gridDim.x - 1) {
            g_bar_cnt = 0;
            __threadfence();
            atomicExch(&g_bar_gen, gen + 1u);
        } else {
            while (*vg == gen) { __nanosleep(64); }
        }
        __threadfence();
    }
    __syncthreads();
}

// 2-way bf16 split of a value pair -> 2 packed bf16x2 words (x low, y high).
__device__ __forceinline__ void split2_pair(float x, float y,
        uint32_t& u1, uint32_t& u2) {
    __nv_bfloat162 b1 = __floats2bfloat162_rn(x, y);
    float rx = x - __bfloat162float(__low2bfloat16(b1));
    float ry = y - __bfloat162float(__high2bfloat16(b1));
    __nv_bfloat162 b2 = __floats2bfloat162_rn(rx, ry);
    u1 = *(uint32_t*)&b1; u2 = *(uint32_t*)&b2;
}

// Write a packed pair (value cols 2q,2q+1 of row m within a 64-row block,
// k-tile kt) into fragment layout at fragment-array word address space.
__device__ __forceinline__ void frag_write(uint32_t* base_words, int strips_nkt_off,
        int m, int q, int kt, uint32_t u1, uint32_t u2) {
    int r_ = m & 15;
    int strip = m >> 4;
    int j = ((r_ >= 8) ? 1 : 0) + ((q >= 4) ? 2 : 0);
    int lanep = (r_ & 7) * 4 + (q & 3);
    size_t i4 = (((size_t)(strips_nkt_off + strip) * NKT + kt) * 2) * 32 + lanep;
    base_words[i4 * 4 + j] = u1;
    base_words[(i4 + 32) * 4 + j] = u2;
}

__device__ __forceinline__ void mma_bf16(float* c, const uint32_t* a,
                                         uint32_t b0, uint32_t b1) {
    asm volatile(
        "mma.sync.aligned.m16n8k16.row.col.f32.bf16.bf16.f32 "
        "{%0,%1,%2,%3}, {%4,%5,%6,%7}, {%8,%9}, {%0,%1,%2,%3};"
        : "+f"(c[0]), "+f"(c[1]), "+f"(c[2]), "+f"(c[3])
        : "r"(a[0]), "r"(a[1]), "r"(a[2]), "r"(a[3]), "r"(b0), "r"(b1));
}

// ---------------------------------------------------------------------------
// K1: gather embeddings
// ---------------------------------------------------------------------------
__global__ void gather_kernel(const int* __restrict__ tokens,
                              const int* __restrict__ ner,
                              const int* __restrict__ pos,
                              const float* __restrict__ encW,
                              const float* __restrict__ nerW,
                              const float* __restrict__ posW) {
    int r = blockIdx.x;
    int b = r & (BB - 1);
    int t = r >> 6;
    int tok = tokens[b * TT + t];
    int nid = ner[b * TT + t];
    int pid = pos[b * TT + t];
    float* dst = g_combined + (size_t)r * CIN;
    for (int c = threadIdx.x; c < CIN; c += blockDim.x) {
        float v;
        if (c < DD)             v = encW[(size_t)tok * DD + c];
        else if (c < DD + NNER) v = nerW[nid * NNER + (c - DD)];
        else                    v = posW[pid * NPOS + (c - DD - NNER)];
        dst[c] = v;
    }
}

// ---------------------------------------------------------------------------
// K2: agg GEMM: x = combined @ aggW^T + aggb, epilogue writes x FRAGMENTS.
// ---------------------------------------------------------------------------
__global__ void gemm_agg_split(const float* __restrict__ A, const float* __restrict__ Bm,
                               const float* __restrict__ bias,
                               int M, int N, int K, int lda, int ldb) {
    __shared__ __align__(16) float As[16 * 64];
    __shared__ __align__(16) float Bs[16 * 64];
    int tid = threadIdx.x;
    int m0 = blockIdx.y * 64;
    int n0 = blockIdx.x * 64;
    int mi = tid & 15;
    int ni = tid >> 4;
    float acc[4][4] = {};

    for (int k0 = 0; k0 < K; k0 += 16) {
        __syncthreads();
        #pragma unroll
        for (int i = 0; i < 4; i++) {
            int e = tid + 256 * i;
            int m = e >> 4, k = e & 15;
            int kk = k0 + k;
            float v = 0.f;
            if (kk < K) v = A[(size_t)(m0 + m) * lda + kk];
            As[k * 64 + m] = v;
        }
        #pragma unroll
        for (int i = 0; i < 4; i++) {
            int e = tid + 256 * i;
            int n = e >> 4, k = e & 15;
            int kk = k0 + k, nn = n0 + n;
            float v = 0.f;
            if (kk < K && nn < N) v = Bm[(size_t)nn * ldb + kk];
            Bs[k * 64 + n] = v;
        }
        __syncthreads();
        #pragma unroll
        for (int k = 0; k < 16; k++) {
            float4 a4 = *(const float4*)(As + k * 64 + mi * 4);
            float4 b4 = *(const float4*)(Bs + k * 64 + ni * 4);
            acc[0][0] = fmaf(a4.x, b4.x, acc[0][0]);
            acc[0][1] = fmaf(a4.x, b4.y, acc[0][1]);
            acc[0][2] = fmaf(a4.x, b4.z, acc[0][2]);
            acc[0][3] = fmaf(a4.x, b4.w, acc[0][3]);
            acc[1][0] = fmaf(a4.y, b4.x, acc[1][0]);
            acc[1][1] = fmaf(a4.y, b4.y, acc[1][1]);
            acc[1][2] = fmaf(a4.y, b4.z, acc[1][2]);
            acc[1][3] = fmaf(a4.y, b4.w, acc[1][3]);
            acc[2][0] = fmaf(a4.z, b4.x, acc[2][0]);
            acc[2][1] = fmaf(a4.z, b4.y, acc[2][1]);
            acc[2][2] = fmaf(a4.z, b4.z, acc[2][2]);
            acc[2][3] = fmaf(a4.z, b4.w, acc[2][3]);
            acc[3][0] = fmaf(a4.w, b4.x, acc[3][0]);
            acc[3][1] = fmaf(a4.w, b4.y, acc[3][1]);
            acc[3][2] = fmaf(a4.w, b4.z, acc[3][2]);
            acc[3][3] = fmaf(a4.w, b4.w, acc[3][3]);
        }
    }
    #pragma unroll
    for (int r = 0; r < 4; r++) {
        int mm = m0 + mi * 4 + r;
        int nn0 = n0 + ni * 4;
        #pragma unroll
        for (int pr = 0; pr < 2; pr++) {
            int nn = nn0 + 2 * pr;
            if (nn < N) {   // N even => both pair elements valid
                float v0 = acc[r][2 * pr]     + bias[nn];
                float v1 = acc[r][2 * pr + 1] + bias[nn + 1];
                uint32_t u1, u2;
                split2_pair(v0, v1, u1, u2);
                frag_write((uint32_t*)g_xf4, 0, mm, (nn >> 1) & 7, nn >> 4, u1, u2);
            }
        }
    }
}

// ---------------------------------------------------------------------------
// K3: pack weights into 2-term bf16 mma-fragment layout (10 matrices:
// 0 = W0 bottom (recurrent), 1..8 = Ws, 9 = W0 top (x path)).
// ---------------------------------------------------------------------------
__global__ void pack_w(const float* __restrict__ W0, const float* __restrict__ Ws) {
    int id = blockIdx.x;
    int pt = id % NTILE;
    int kt = (id / NTILE) % NKT;
    int mat = id / (NTILE * NKT);
    int ns = threadIdx.x >> 5;
    int lane = threadIdx.x & 31;
    const float* W = (mat == 0) ? (W0 + (size_t)DD * D2)
                   : (mat == 9) ? W0
                                : (Ws + (size_t)(mat - 1) * DD * D2);
    int half = ns >> 1;
    int col = pt * 16 + (ns & 1) * 8 + (lane >> 2);
    int gcol = (col < DD) ? (half ? DD + col : col) : -1;
    int k0 = kt * 16 + (lane & 3) * 2;
    float v[4];
    #pragma unroll
    for (int j = 0; j < 4; ++j) {
        int k = k0 + (j & 1) + (j >> 1) * 8;   // k0, k0+1, k0+8, k0+9
        v[j] = (gcol >= 0 && k < DD) ? W[(size_t)k * D2 + gcol] : 0.f;
    }
    uint32_t a1, a2, b1, b2;
    split2_pair(v[0], v[1], a1, a2);
    split2_pair(v[2], v[3], b1, b2);
    g_Wf4[((size_t)id * 4 + ns) * 32 + lane] = make_uint4(a1, b1, a2, b2);
}

// ---------------------------------------------------------------------------
// K4: xw0 = x @ W0top via fragment mma. grid = (54 tiles, 256 m-blocks).
// 8 warps = ng(2) x m16i(2) x kh(2); kh partials combined via smem.
// ---------------------------------------------------------------------------
__global__ __launch_bounds__(256)
void xw0_mma() {
    __shared__ float sm[2][32][33];
    const int tile = blockIdx.x;
    const int mb = blockIdx.y;
    const int tid = threadIdx.x;
    const int lane = tid & 31;
    const int w = tid >> 5;
    const int ng = w & 1;
    const int m16i = (w >> 1) & 1;
    const int kh = w >> 2;

    const int strip = mb * 2 + m16i;
    const uint4* __restrict__ Abase = g_xf4 + ((size_t)strip * NKT) * 2 * 32 + lane;

    float c0[4] = {0.f, 0.f, 0.f, 0.f};
    float c1[4] = {0.f, 0.f, 0.f, 0.f};

    const int ktb = kh * 27;
    #pragma unroll 3
    for (int kt = ktb; kt < ktb + 27; ++kt) {
        uint4 A1v = Abase[(size_t)kt * 64];
        uint4 A2v = Abase[(size_t)kt * 64 + 32];
        uint32_t a1[4] = {A1v.x, A1v.y, A1v.z, A1v.w};
        uint32_t a2[4] = {A2v.x, A2v.y, A2v.z, A2v.w};
        size_t wb = ((size_t)((9 * NKT + kt) * NTILE + tile) * 4 + ng * 2) * 32 + lane;
        uint4 w40 = g_Wf4[wb];
        uint4 w41 = g_Wf4[wb + 32];
        mma_bf16(c0, a1, w40.x, w40.y);
        mma_bf16(c0, a1, w40.z, w40.w);
        mma_bf16(c0, a2, w40.x, w40.y);
        mma_bf16(c1, a1, w41.x, w41.y);
        mma_bf16(c1, a1, w41.z, w41.w);
        mma_bf16(c1, a2, w41.x, w41.y);
    }

    {
        const int rl = m16i * 16 + (lane >> 2);
        const int cb = ng * 16 + (lane & 3) * 2;
        sm[kh][rl][cb]         = c0[0];
        sm[kh][rl][cb + 1]     = c0[1];
        sm[kh][rl + 8][cb]     = c0[2];
        sm[kh][rl + 8][cb + 1] = c0[3];
        sm[kh][rl][cb + 8]         = c1[0];
        sm[kh][rl][cb + 9]         = c1[1];
        sm[kh][rl + 8][cb + 8]     = c1[2];
        sm[kh][rl + 8][cb + 9]     = c1[3];
    }
    __syncthreads();

    const int ml = tid >> 3;
    const int q = tid & 7;
    const int p0 = tile * 16 + 2 * q;
    const int row = mb * 32 + ml;
    if (p0 < DD) {
        float cc0 = sm[0][ml][2 * q]     + sm[1][ml][2 * q];
        float cc1 = sm[0][ml][2 * q + 1] + sm[1][ml][2 * q + 1];
        float hh0 = sm[0][ml][16 + 2 * q]     + sm[1][ml][16 + 2 * q];
        float hh1 = sm[0][ml][16 + 2 * q + 1] + sm[1][ml][16 + 2 * q + 1];
        float* xw = g_xw0 + (size_t)row * D2;
        __stcs((float2*)&xw[p0],      make_float2(cc0, cc1));
        __stcs((float2*)&xw[DD + p0], make_float2(hh0, hh1));
    }
}

// ---------------------------------------------------------------------------
// One recurrence job: C[32 rows x (16c+16h)] full-K, 3-pass 2-way-split mma.
// 8 warps = ng(2) x m16i(2) x khalf(2); khalf partials combined via smem.
// A operands read as coalesced uint4 fragments (g_af4).
// Level 4 jobs additionally fold next-step prep via per-(mh,tile) counter.
// ---------------------------------------------------------------------------
__device__ __forceinline__ void do_job(
    int t, int lvl, int j, float (*sm)[32][33], int* s_old)
{
    const int tile = j % NTILE;
    const int r = j / NTILE;
    const int mh = r & 1;
    const int mi = r >> 1;
    const int sid = c_sid[lvl][mi];
    const StepInfo si = c_steps[sid];
    const int asrc = (si.pred < 0) ? 9 : si.pred;
    const float* __restrict__ Afp = (si.pred < 0) ? g_hprev : g_state[si.pred];

    const int tid = threadIdx.x;
    const int lane = tid & 31;
    const int w = tid >> 5;
    const int ng = w & 1;
    const int m16i = (w >> 1) & 1;
    const int kh = w >> 2;

    const int strip = mh * 2 + m16i;
    const uint4* __restrict__ Abase =
        g_af4 + ((size_t)(asrc * 4 + strip) * NKT) * 2 * 32 + lane;

    float c0[4] = {0.f, 0.f, 0.f, 0.f};
    float c1[4] = {0.f, 0.f, 0.f, 0.f};

    const int ktb = kh * 27;
    #pragma unroll 3
    for (int kt = ktb; kt < ktb + 27; ++kt) {
        uint4 A1v = Abase[(size_t)kt * 64];
        uint4 A2v = Abase[(size_t)kt * 64 + 32];
        uint32_t a1[4] = {A1v.x, A1v.y, A1v.z, A1v.w};
        uint32_t a2[4] = {A2v.x, A2v.y, A2v.z, A2v.w};
        size_t wb = ((size_t)((si.wmat * NKT + kt) * NTILE + tile) * 4 + ng * 2) * 32 + lane;
        uint4 w40 = g_Wf4[wb];
        uint4 w41 = g_Wf4[wb + 32];
        mma_bf16(c0, a1, w40.x, w40.y);   // x1*w1
        mma_bf16(c0, a1, w40.z, w40.w);   // x1*w2
        mma_bf16(c0, a2, w40.x, w40.y);   // x2*w1
        mma_bf16(c1, a1, w41.x, w41.y);
        mma_bf16(c1, a1, w41.z, w41.w);
        mma_bf16(c1, a2, w41.x, w41.y);
    }

    // store fragments to smem (khalf-partials)
    {
        const int rl = m16i * 16 + (lane >> 2);
        const int cb = ng * 16 + (lane & 3) * 2;
        sm[kh][rl][cb]         = c0[0];
        sm[kh][rl][cb + 1]     = c0[1];
        sm[kh][rl + 8][cb]     = c0[2];
        sm[kh][rl + 8][cb + 1] = c0[3];
        sm[kh][rl][cb + 8]         = c1[0];
        sm[kh][rl][cb + 9]         = c1[1];
        sm[kh][rl + 8][cb + 8]     = c1[2];
        sm[kh][rl + 8][cb + 9]     = c1[3];
    }
    __syncthreads();

    // epilogue: 256 threads = 32 rows x 8 col-pairs
    const int ml = tid >> 3;
    const int q = tid & 7;
    const int p0 = tile * 16 + 2 * q;
    const int m = mh * 32 + ml;
    if (p0 < DD) {
        float vv[2];
        #pragma unroll
        for (int e = 0; e < 2; ++e) {
            int cp = 2 * q + e;
            int p = p0 + e;
            float cc = sm[0][ml][cp] + sm[1][ml][cp];
            float hh = sm[0][ml][16 + cp] + sm[1][ml][16 + cp];
            if (si.pred < 0) {
                const float* xw = g_xw0 + ((size_t)t * BB + m) * D2;
                cc += __ldcs(xw + p);
                hh += __ldcs(xw + DD + p);
            }
            float sp = Afp[(size_t)m * SD + p];
            float g = 1.f / (1.f + expf(-cc));
            float av = (si.act == 0) ? tanhf(hh)
                     : (si.act == 1) ? fmaxf(hh, 0.f)
                     : (si.act == 2) ? 1.f / (1.f + expf(-hh)) : hh;
            vv[e] = sp + g * (av - sp);
        }
        *(float2*)&g_state[sid][(size_t)m * SD + p0] = make_float2(vv[0], vv[1]);
        uint32_t u1, u2;
        split2_pair(vv[0], vv[1], u1, u2);
        frag_write((uint32_t*)g_af4, sid * 4, m, q, tile, u1, u2);
    }
    __syncthreads();   // smem reusable by next job

    // level-4 fold: when both mats (6,8) of this (mh,tile) block are done,
    // compute next-step hprev (+ hiddens[t]) for these rows/cols.
    if (lvl == 4) {
        __threadfence();
        __syncthreads();
        if (tid == 0) *s_old = atomicAdd(&g_tcnt[mh * 54 + tile], 1);
        __syncthreads();
        if (*s_old == 1) {
            __threadfence();
            if (p0 < DD) {
                float v0 = 0.f, v1 = 0.f;
                #pragma unroll
                for (int jj = 1; jj <= 8; ++jj) {
                    v0 += g_state[jj][(size_t)m * SD + p0];
                    v1 += g_state[jj][(size_t)m * SD + p0 + 1];
                }
                v0 *= 0.125f;
                v1 *= 0.125f;
                *(float2*)&g_hprev[(size_t)m * SD + p0] = make_float2(v0, v1);
                *(float2*)&g_hiddens[(size_t)t * BB * DD + (size_t)m * DD + p0]
                    = make_float2(v0, v1);
                uint32_t u1, u2;
                split2_pair(v0, v1, u1, u2);
                frag_write((uint32_t*)g_af4, 9 * 4, m, q, tile, u1, u2);
            }
            __syncthreads();
            if (tid == 0) g_tcnt[mh * 54 + tile] = 0;
        }
        __syncthreads();
    }
}

__global__ __launch_bounds__(256, 2)
void recur_persist(const float* __restrict__ hidden) {
    __shared__ float sm[2][32][33];
    __shared__ int s_old;
    const int bid = blockIdx.x;
    const int G = gridDim.x;
    const int tid = threadIdx.x;

    // initial prep (t = 0): hprev = hidden, plus fragment splits
    for (int i = bid * 256 + tid; i < BB * 425; i += G * 256) {
        int m = i / 425;
        int qd = i - m * 425;
        int d0 = 2 * qd;
        float v0 = hidden[m * DD + d0];
        float v1 = hidden[m * DD + d0 + 1];
        *(float2*)&g_hprev[(size_t)m * SD + d0] = make_float2(v0, v1);
        uint32_t u1, u2;
        split2_pair(v0, v1, u1, u2);
        frag_write((uint32_t*)g_af4, 9 * 4, m, qd & 7, d0 >> 4, u1, u2);
    }
    grid_sync();

    for (int t = 0; t < TT; ++t) {
        #pragma unroll
        for (int lvl = 0; lvl < 5; ++lvl) {
            const int jobs = c_nm[lvl] * 108;
            for (int j = bid; j < jobs; j += G)
                do_job(t, lvl, j, sm, &s_old);
            grid_sync();
        }
    }
}

// ---------------------------------------------------------------------------
// K5: mean over T, decoder, log_softmax, new_hidden.
// ---------------------------------------------------------------------------
__global__ void final_kernel(const float* __restrict__ masks,
                             const float* __restrict__ decW,
                             const float* __restrict__ decb,
                             float* __restrict__ out) {
    int b = blockIdx.x;
    int tid = threadIdx.x;
    __shared__ float sout[DD];
    __shared__ float lg[NCC];
    __shared__ float lse;

    float mask_last = masks[b * TT + TT - 1];
    for (int d = tid; d < DD; d += blockDim.x) {
        float ms = 0.f;
        #pragma unroll
        for (int j = 1; j <= 8; j++) ms += g_state[j][b * SD + d];
        ms *= 0.125f;
        float last_raw = ms * mask_last;
        float acc = last_raw;
        for (int t = 0; t < TT - 1; t++)
            acc += g_hiddens[(size_t)t * BB * DD + b * DD + d] * masks[b * TT + t];
        sout[d] = acc * (1.f / TT);
        out[NCC * BB + b * DD + d] = last_raw;
    }
    __syncthreads();

    for (int c = tid; c < NCC; c += blockDim.x) {
        float acc = decb[c];
        const float* w = decW + (size_t)c * DD;
        for (int d = 0; d < DD; d++) acc = fmaf(sout[d], w[d], acc);
        lg[c] = acc;
    }
    __syncthreads();

    if (tid == 0) {
        float mx = lg[0];
        for (int c = 1; c < NCC; c++) mx = fmaxf(mx, lg[c]);
        float s = 0.f;
        for (int c = 0; c < NCC; c++) s += expf(lg[c] - mx);
        lse = mx + logf(s);
    }
    __syncthreads();

    for (int c = tid; c < NCC; c += blockDim.x)
        out[b * NCC + c] = lg[c] - lse;
}

// ---------------------------------------------------------------------------
// Host launcher
// ---------------------------------------------------------------------------
extern "C" void kernel_launch(void* const* d_in, const int* in_sizes, int n_in,
                              void* d_out, int out_size) {
    const int*   tokens = (const int*)  d_in[0];
    const float* masks  = (const float*)d_in[1];
    const int*   pos    = (const int*)  d_in[2];
    const int*   ner    = (const int*)  d_in[3];
    const float* hidden = (const float*)d_in[4];
    const float* encW   = (const float*)d_in[5];
    const float* nerW   = (const float*)d_in[6];
    const float* posW   = (const float*)d_in[7];
    const float* aggW   = (const float*)d_in[8];
    const float* aggb   = (const float*)d_in[9];
    const float* W0     = (const float*)d_in[10];
    const float* Ws     = (const float*)d_in[11];
    const float* decW   = (const float*)d_in[12];
    const float* decb   = (const float*)d_in[13];
    float* out = (float*)d_out;

    static int s_grid = 0;
    if (s_grid == 0) {
        int dev = 0;
        cudaGetDevice(&dev);
        cudaDeviceProp prop;
        cudaGetDeviceProperties(&prop, dev);
        s_grid = prop.multiProcessorCount;   // 1 CTA/SM: co-resident, cheap barrier
    }

    float* p_combined;
    cudaGetSymbolAddress((void**)&p_combined, g_combined);

    // 1) gather embeddings + pack weights (independent)
    gather_kernel<<<TT * BB, 128>>>(tokens, ner, pos, encW, nerW, posW);
    pack_w<<<WMATS * NKT * NTILE, 128>>>(W0, Ws);

    // 2) agg linear -> x fragments   [8192, 850]
    {
        dim3 g((DD + 63) / 64, (TT * BB) / 64);
        gemm_agg_split<<<g, 256>>>(p_combined, aggW, aggb,
                                   TT * BB, DD, CIN, CIN, CIN);
    }
    // 3) xw0 = x @ W0top via fragment mma   [8192, 1700]
    xw0_mma<<<dim3(NTILE, (TT * BB) / 32), 256>>>();

    // 4) whole recurrence in ONE persistent kernel
    recur_persist<<<s_grid, 256>>>(hidden);

    // 5) mean over T, decoder, log_softmax, new_hidden
    final_kernel<<<BB, 256>>>(masks, decW, decb, out);
}

// round 16
// speedup vs baseline: 2.1609x; 1.1879x over previous
#include <cuda_runtime.h>
#include <cuda_bf16.h>
#include <math.h>
#include <stdint.h>

#define BB   64
#define TT   128
#define DD   850
#define D2   1700
#define CIN  910
#define NCC  42
#define NNER 30
#define NPOS 30
#define SD   864          // padded k stride; pads stay zero
#define NTILE 54          // 16-col pair tiles
#define NKT  54           // k16 tiles
#define WMATS 10          // 0..8 recurrent (W0bot, Ws[0..7]); 9 = W0top
#define XSTRIPS (TT * BB / 16)   // 512 row-strips of x
#define MAXG 512

// Scratch (device globals zero-initialized; pad regions never written)
__device__ float g_combined[TT * BB * CIN];
__device__ float g_xw0[TT * BB * D2];
__device__ float g_hiddens[TT * BB * DD];
__device__ float g_state[9][BB * SD];
__device__ float g_hprev[BB * SD];
__device__ int   g_tcnt[108];          // fold counters: mh*54 + tile
__device__ unsigned g_flags[MAXG];     // per-CTA arrival generation
__device__ volatile unsigned g_bcast;  // broadcast generation
__device__ unsigned g_gen_base;        // persistent across launches
// W fragments (2-way split): idx = ((wmat*NKT+kt)*NTILE+tile)*4 + ns, per lane.
__device__ __align__(256) uint4 g_Wf4[WMATS * NKT * NTILE * 4 * 32];
// A fragments (states 0..8, hprev=9), mma-A layout:
// uint4 per lane = {j0,j1,j2,j3}; idx = ((src*4+strip)*NKT+kt)*2 + term, x32 lanes
__device__ __align__(256) uint4 g_af4[10 * 4 * NKT * 2 * 32];
// x fragments for xw0 mma: idx = ((strip*NKT+kt)*2 + term) x32 lanes
__device__ __align__(256) uint4 g_xf4[(size_t)XSTRIPS * NKT * 2 * 32];

struct StepInfo { int wmat; int pred; int act; };
// act: 0 tanh, 1 relu, 2 sigmoid, 3 identity
__constant__ StepInfo c_steps[9] = {
    {0, -1, 0}, {1, 0, 2}, {2, 1, 1}, {3, 1, 1}, {4, 1, 3},
    {5, 2, 0}, {6, 5, 2}, {7, 3, 0}, {8, 5, 1},
};
// Levels: {s0},{s1},{s2,s3,s4},{s5,s7},{s6,s8}
__constant__ int c_nm[5]     = {1, 1, 3, 2, 2};
__constant__ int c_sid[5][3] = {{0,0,0},{1,1,1},{2,3,4},{5,7,7},{6,8,8}};

// Flag-array grid barrier, generation-based (equality compare: wrap-safe).
// All CTAs co-resident (launch_bounds(256,2), grid = 2*SMs).
__device__ __forceinline__ void grid_sync2(unsigned gen) {
    __syncthreads();
    if (blockIdx.x == 0) {
        for (int i = 1 + threadIdx.x; i < (int)gridDim.x; i += blockDim.x) {
            while (((volatile unsigned*)g_flags)[i] != gen) { __nanosleep(32); }
        }
        __syncthreads();
        if (threadIdx.x == 0) {
            __threadfence();
            g_bcast = gen;
        }
        __syncthreads();
    } else {
        if (threadIdx.x == 0) {
            __threadfence();
            ((volatile unsigned*)g_flags)[blockIdx.x] = gen;
            while (g_bcast != gen) { __nanosleep(32); }
            __threadfence();
        }
        __syncthreads();
    }
}

// 2-way bf16 split of a value pair -> 2 packed bf16x2 words (x low, y high).
__device__ __forceinline__ void split2_pair(float x, float y,
        uint32_t& u1, uint32_t& u2) {
    __nv_bfloat162 b1 = __floats2bfloat162_rn(x, y);
    float rx = x - __bfloat162float(__low2bfloat16(b1));
    float ry = y - __bfloat162float(__high2bfloat16(b1));
    __nv_bfloat162 b2 = __floats2bfloat162_rn(rx, ry);
    u1 = *(uint32_t*)&b1; u2 = *(uint32_t*)&b2;
}

// Write a packed pair (value cols 2q,2q+1 of row m within a 64-row block,
// k-tile kt) into fragment layout at fragment-array word address space.
__device__ __forceinline__ void frag_write(uint32_t* base_words, int strips_nkt_off,
        int m, int q, int kt, uint32_t u1, uint32_t u2) {
    int r_ = m & 15;
    int strip = m >> 4;
    int j = ((r_ >= 8) ? 1 : 0) + ((q >= 4) ? 2 : 0);
    int lanep = (r_ & 7) * 4 + (q & 3);
    size_t i4 = (((size_t)(strips_nkt_off + strip) * NKT + kt) * 2) * 32 + lanep;
    base_words[i4 * 4 + j] = u1;
    base_words[(i4 + 32) * 4 + j] = u2;
}

__device__ __forceinline__ void mma_bf16(float* c, const uint32_t* a,
                                         uint32_t b0, uint32_t b1) {
    asm volatile(
        "mma.sync.aligned.m16n8k16.row.col.f32.bf16.bf16.f32 "
        "{%0,%1,%2,%3}, {%4,%5,%6,%7}, {%8,%9}, {%0,%1,%2,%3};"
        : "+f"(c[0]), "+f"(c[1]), "+f"(c[2]), "+f"(c[3])
        : "r"(a[0]), "r"(a[1]), "r"(a[2]), "r"(a[3]), "r"(b0), "r"(b1));
}

// ---------------------------------------------------------------------------
// K1: gather embeddings
// ---------------------------------------------------------------------------
__global__ void gather_kernel(const int* __restrict__ tokens,
                              const int* __restrict__ ner,
                              const int* __restrict__ pos,
                              const float* __restrict__ encW,
                              const float* __restrict__ nerW,
                              const float* __restrict__ posW) {
    int r = blockIdx.x;
    int b = r & (BB - 1);
    int t = r >> 6;
    int tok = tokens[b * TT + t];
    int nid = ner[b * TT + t];
    int pid = pos[b * TT + t];
    float* dst = g_combined + (size_t)r * CIN;
    for (int c = threadIdx.x; c < CIN; c += blockDim.x) {
        float v;
        if (c < DD)             v = encW[(size_t)tok * DD + c];
        else if (c < DD + NNER) v = nerW[nid * NNER + (c - DD)];
        else                    v = posW[pid * NPOS + (c - DD - NNER)];
        dst[c] = v;
    }
}

// ---------------------------------------------------------------------------
// K2: agg GEMM: x = combined @ aggW^T + aggb, epilogue writes x FRAGMENTS.
// ---------------------------------------------------------------------------
__global__ void gemm_agg_split(const float* __restrict__ A, const float* __restrict__ Bm,
                               const float* __restrict__ bias,
                               int M, int N, int K, int lda, int ldb) {
    __shared__ __align__(16) float As[16 * 64];
    __shared__ __align__(16) float Bs[16 * 64];
    int tid = threadIdx.x;
    int m0 = blockIdx.y * 64;
    int n0 = blockIdx.x * 64;
    int mi = tid & 15;
    int ni = tid >> 4;
    float acc[4][4] = {};

    for (int k0 = 0; k0 < K; k0 += 16) {
        __syncthreads();
        #pragma unroll
        for (int i = 0; i < 4; i++) {
            int e = tid + 256 * i;
            int m = e >> 4, k = e & 15;
            int kk = k0 + k;
            float v = 0.f;
            if (kk < K) v = A[(size_t)(m0 + m) * lda + kk];
            As[k * 64 + m] = v;
        }
        #pragma unroll
        for (int i = 0; i < 4; i++) {
            int e = tid + 256 * i;
            int n = e >> 4, k = e & 15;
            int kk = k0 + k, nn = n0 + n;
            float v = 0.f;
            if (kk < K && nn < N) v = Bm[(size_t)nn * ldb + kk];
            Bs[k * 64 + n] = v;
        }
        __syncthreads();
        #pragma unroll
        for (int k = 0; k < 16; k++) {
            float4 a4 = *(const float4*)(As + k * 64 + mi * 4);
            float4 b4 = *(const float4*)(Bs + k * 64 + ni * 4);
            acc[0][0] = fmaf(a4.x, b4.x, acc[0][0]);
            acc[0][1] = fmaf(a4.x, b4.y, acc[0][1]);
            acc[0][2] = fmaf(a4.x, b4.z, acc[0][2]);
            acc[0][3] = fmaf(a4.x, b4.w, acc[0][3]);
            acc[1][0] = fmaf(a4.y, b4.x, acc[1][0]);
            acc[1][1] = fmaf(a4.y, b4.y, acc[1][1]);
            acc[1][2] = fmaf(a4.y, b4.z, acc[1][2]);
            acc[1][3] = fmaf(a4.y, b4.w, acc[1][3]);
            acc[2][0] = fmaf(a4.z, b4.x, acc[2][0]);
            acc[2][1] = fmaf(a4.z, b4.y, acc[2][1]);
            acc[2][2] = fmaf(a4.z, b4.z, acc[2][2]);
            acc[2][3] = fmaf(a4.z, b4.w, acc[2][3]);
            acc[3][0] = fmaf(a4.w, b4.x, acc[3][0]);
            acc[3][1] = fmaf(a4.w, b4.y, acc[3][1]);
            acc[3][2] = fmaf(a4.w, b4.z, acc[3][2]);
            acc[3][3] = fmaf(a4.w, b4.w, acc[3][3]);
        }
    }
    #pragma unroll
    for (int r = 0; r < 4; r++) {
        int mm = m0 + mi * 4 + r;
        int nn0 = n0 + ni * 4;
        #pragma unroll
        for (int pr = 0; pr < 2; pr++) {
            int nn = nn0 + 2 * pr;
            if (nn < N) {   // N even => both pair elements valid
                float v0 = acc[r][2 * pr]     + bias[nn];
                float v1 = acc[r][2 * pr + 1] + bias[nn + 1];
                uint32_t u1, u2;
                split2_pair(v0, v1, u1, u2);
                frag_write((uint32_t*)g_xf4, 0, mm, (nn >> 1) & 7, nn >> 4, u1, u2);
            }
        }
    }
}

// ---------------------------------------------------------------------------
// K3: pack weights into 2-term bf16 mma-fragment layout (10 matrices:
// 0 = W0 bottom (recurrent), 1..8 = Ws, 9 = W0 top (x path)).
// ---------------------------------------------------------------------------
__global__ void pack_w(const float* __restrict__ W0, const float* __restrict__ Ws) {
    int id = blockIdx.x;
    int pt = id % NTILE;
    int kt = (id / NTILE) % NKT;
    int mat = id / (NTILE * NKT);
    int ns = threadIdx.x >> 5;
    int lane = threadIdx.x & 31;
    const float* W = (mat == 0) ? (W0 + (size_t)DD * D2)
                   : (mat == 9) ? W0
                                : (Ws + (size_t)(mat - 1) * DD * D2);
    int half = ns >> 1;
    int col = pt * 16 + (ns & 1) * 8 + (lane >> 2);
    int gcol = (col < DD) ? (half ? DD + col : col) : -1;
    int k0 = kt * 16 + (lane & 3) * 2;
    float v[4];
    #pragma unroll
    for (int j = 0; j < 4; ++j) {
        int k = k0 + (j & 1) + (j >> 1) * 8;   // k0, k0+1, k0+8, k0+9
        v[j] = (gcol >= 0 && k < DD) ? W[(size_t)k * D2 + gcol] : 0.f;
    }
    uint32_t a1, a2, b1, b2;
    split2_pair(v[0], v[1], a1, a2);
    split2_pair(v[2], v[3], b1, b2);
    g_Wf4[((size_t)id * 4 + ns) * 32 + lane] = make_uint4(a1, b1, a2, b2);
}

// ---------------------------------------------------------------------------
// K4: xw0 = x @ W0top via fragment mma. grid = (54 tiles, 256 m-blocks).
// ---------------------------------------------------------------------------
__global__ __launch_bounds__(256)
void xw0_mma() {
    __shared__ float sm[2][32][33];
    const int tile = blockIdx.x;
    const int mb = blockIdx.y;
    const int tid = threadIdx.x;
    const int lane = tid & 31;
    const int w = tid >> 5;
    const int ng = w & 1;
    const int m16i = (w >> 1) & 1;
    const int kh = w >> 2;

    const int strip = mb * 2 + m16i;
    const uint4* __restrict__ Abase = g_xf4 + ((size_t)strip * NKT) * 2 * 32 + lane;

    float c0[4] = {0.f, 0.f, 0.f, 0.f};
    float c1[4] = {0.f, 0.f, 0.f, 0.f};

    const int ktb = kh * 27;
    #pragma unroll 3
    for (int kt = ktb; kt < ktb + 27; ++kt) {
        uint4 A1v = Abase[(size_t)kt * 64];
        uint4 A2v = Abase[(size_t)kt * 64 + 32];
        uint32_t a1[4] = {A1v.x, A1v.y, A1v.z, A1v.w};
        uint32_t a2[4] = {A2v.x, A2v.y, A2v.z, A2v.w};
        size_t wb = ((size_t)((9 * NKT + kt) * NTILE + tile) * 4 + ng * 2) * 32 + lane;
        uint4 w40 = g_Wf4[wb];
        uint4 w41 = g_Wf4[wb + 32];
        mma_bf16(c0, a1, w40.x, w40.y);
        mma_bf16(c0, a1, w40.z, w40.w);
        mma_bf16(c0, a2, w40.x, w40.y);
        mma_bf16(c1, a1, w41.x, w41.y);
        mma_bf16(c1, a1, w41.z, w41.w);
        mma_bf16(c1, a2, w41.x, w41.y);
    }

    {
        const int rl = m16i * 16 + (lane >> 2);
        const int cb = ng * 16 + (lane & 3) * 2;
        sm[kh][rl][cb]         = c0[0];
        sm[kh][rl][cb + 1]     = c0[1];
        sm[kh][rl + 8][cb]     = c0[2];
        sm[kh][rl + 8][cb + 1] = c0[3];
        sm[kh][rl][cb + 8]         = c1[0];
        sm[kh][rl][cb + 9]         = c1[1];
        sm[kh][rl + 8][cb + 8]     = c1[2];
        sm[kh][rl + 8][cb + 9]     = c1[3];
    }
    __syncthreads();

    const int ml = tid >> 3;
    const int q = tid & 7;
    const int p0 = tile * 16 + 2 * q;
    const int row = mb * 32 + ml;
    if (p0 < DD) {
        float cc0 = sm[0][ml][2 * q]     + sm[1][ml][2 * q];
        float cc1 = sm[0][ml][2 * q + 1] + sm[1][ml][2 * q + 1];
        float hh0 = sm[0][ml][16 + 2 * q]     + sm[1][ml][16 + 2 * q];
        float hh1 = sm[0][ml][16 + 2 * q + 1] + sm[1][ml][16 + 2 * q + 1];
        float* xw = g_xw0 + (size_t)row * D2;
        __stcs((float2*)&xw[p0],      make_float2(cc0, cc1));
        __stcs((float2*)&xw[DD + p0], make_float2(hh0, hh1));
    }
}

// ---------------------------------------------------------------------------
// One recurrence job: C[32 rows x (16c+16h)] full-K, 3-pass 2-way-split mma.
// 8 warps = ng(2) x m16i(2) x khalf(2); khalf partials combined via smem.
// A operands read as coalesced uint4 fragments (g_af4).
// Level 4 jobs additionally fold next-step prep via per-(mh,tile) counter.
// ---------------------------------------------------------------------------
__device__ __forceinline__ void do_job(
    int t, int lvl, int j, float (*sm)[32][33], int* s_old)
{
    const int tile = j % NTILE;
    const int r = j / NTILE;
    const int mh = r & 1;
    const int mi = r >> 1;
    const int sid = c_sid[lvl][mi];
    const StepInfo si = c_steps[sid];
    const int asrc = (si.pred < 0) ? 9 : si.pred;
    const float* __restrict__ Afp = (si.pred < 0) ? g_hprev : g_state[si.pred];

    const int tid = threadIdx.x;
    const int lane = tid & 31;
    const int w = tid >> 5;
    const int ng = w & 1;
    const int m16i = (w >> 1) & 1;
    const int kh = w >> 2;

    const int strip = mh * 2 + m16i;
    const uint4* __restrict__ Abase =
        g_af4 + ((size_t)(asrc * 4 + strip) * NKT) * 2 * 32 + lane;

    float c0[4] = {0.f, 0.f, 0.f, 0.f};
    float c1[4] = {0.f, 0.f, 0.f, 0.f};

    const int ktb = kh * 27;
    #pragma unroll 3
    for (int kt = ktb; kt < ktb + 27; ++kt) {
        uint4 A1v = Abase[(size_t)kt * 64];
        uint4 A2v = Abase[(size_t)kt * 64 + 32];
        uint32_t a1[4] = {A1v.x, A1v.y, A1v.z, A1v.w};
        uint32_t a2[4] = {A2v.x, A2v.y, A2v.z, A2v.w};
        size_t wb = ((size_t)((si.wmat * NKT + kt) * NTILE + tile) * 4 + ng * 2) * 32 + lane;
        uint4 w40 = g_Wf4[wb];
        uint4 w41 = g_Wf4[wb + 32];
        mma_bf16(c0, a1, w40.x, w40.y);   // x1*w1
        mma_bf16(c0, a1, w40.z, w40.w);   // x1*w2
        mma_bf16(c0, a2, w40.x, w40.y);   // x2*w1
        mma_bf16(c1, a1, w41.x, w41.y);
        mma_bf16(c1, a1, w41.z, w41.w);
        mma_bf16(c1, a2, w41.x, w41.y);
    }

    // store fragments to smem (khalf-partials)
    {
        const int rl = m16i * 16 + (lane >> 2);
        const int cb = ng * 16 + (lane & 3) * 2;
        sm[kh][rl][cb]         = c0[0];
        sm[kh][rl][cb + 1]     = c0[1];
        sm[kh][rl + 8][cb]     = c0[2];
        sm[kh][rl + 8][cb + 1] = c0[3];
        sm[kh][rl][cb + 8]         = c1[0];
        sm[kh][rl][cb + 9]         = c1[1];
        sm[kh][rl + 8][cb + 8]     = c1[2];
        sm[kh][rl + 8][cb + 9]     = c1[3];
    }
    __syncthreads();

    // epilogue: 256 threads = 32 rows x 8 col-pairs
    const int ml = tid >> 3;
    const int q = tid & 7;
    const int p0 = tile * 16 + 2 * q;
    const int m = mh * 32 + ml;
    if (p0 < DD) {
        float vv[2];
        #pragma unroll
        for (int e = 0; e < 2; ++e) {
            int cp = 2 * q + e;
            int p = p0 + e;
            float cc = sm[0][ml][cp] + sm[1][ml][cp];
            float hh = sm[0][ml][16 + cp] + sm[1][ml][16 + cp];
            if (si.pred < 0) {
                const float* xw = g_xw0 + ((size_t)t * BB + m) * D2;
                cc += __ldcs(xw + p);
                hh += __ldcs(xw + DD + p);
            }
            float sp = Afp[(size_t)m * SD + p];
            float g = 1.f / (1.f + expf(-cc));
            float av = (si.act == 0) ? tanhf(hh)
                     : (si.act == 1) ? fmaxf(hh, 0.f)
                     : (si.act == 2) ? 1.f / (1.f + expf(-hh)) : hh;
            vv[e] = sp + g * (av - sp);
        }
        *(float2*)&g_state[sid][(size_t)m * SD + p0] = make_float2(vv[0], vv[1]);
        uint32_t u1, u2;
        split2_pair(vv[0], vv[1], u1, u2);
        frag_write((uint32_t*)g_af4, sid * 4, m, q, tile, u1, u2);
    }
    __syncthreads();   // smem reusable by next job

    // level-4 fold: when both mats (6,8) of this (mh,tile) block are done,
    // compute next-step hprev (+ hiddens[t]) for these rows/cols.
    if (lvl == 4) {
        __threadfence();
        __syncthreads();
        if (tid == 0) *s_old = atomicAdd(&g_tcnt[mh * 54 + tile], 1);
        __syncthreads();
        if (*s_old == 1) {
            __threadfence();
            if (p0 < DD) {
                float v0 = 0.f, v1 = 0.f;
                #pragma unroll
                for (int jj = 1; jj <= 8; ++jj) {
                    v0 += g_state[jj][(size_t)m * SD + p0];
                    v1 += g_state[jj][(size_t)m * SD + p0 + 1];
                }
                v0 *= 0.125f;
                v1 *= 0.125f;
                *(float2*)&g_hprev[(size_t)m * SD + p0] = make_float2(v0, v1);
                *(float2*)&g_hiddens[(size_t)t * BB * DD + (size_t)m * DD + p0]
                    = make_float2(v0, v1);
                uint32_t u1, u2;
                split2_pair(v0, v1, u1, u2);
                frag_write((uint32_t*)g_af4, 9 * 4, m, q, tile, u1, u2);
            }
            __syncthreads();
            if (tid == 0) g_tcnt[mh * 54 + tile] = 0;
        }
        __syncthreads();
    }
}

__global__ __launch_bounds__(256, 2)
void recur_persist(const float* __restrict__ hidden) {
    __shared__ float sm[2][32][33];
    __shared__ int s_old;
    const int bid = blockIdx.x;
    const int G = gridDim.x;
    const int tid = threadIdx.x;

    unsigned gen = g_gen_base;   // L1 cold at launch; consistent across CTAs

    // initial prep (t = 0): hprev = hidden, plus fragment splits
    for (int i = bid * 256 + tid; i < BB * 425; i += G * 256) {
        int m = i / 425;
        int qd = i - m * 425;
        int d0 = 2 * qd;
        float v0 = hidden[m * DD + d0];
        float v1 = hidden[m * DD + d0 + 1];
        *(float2*)&g_hprev[(size_t)m * SD + d0] = make_float2(v0, v1);
        uint32_t u1, u2;
        split2_pair(v0, v1, u1, u2);
        frag_write((uint32_t*)g_af4, 9 * 4, m, qd & 7, d0 >> 4, u1, u2);
    }
    gen++;
    grid_sync2(gen);

    for (int t = 0; t < TT; ++t) {
        #pragma unroll
        for (int lvl = 0; lvl < 5; ++lvl) {
            const int jobs = c_nm[lvl] * 108;
            for (int j = bid; j < jobs; j += G)
                do_job(t, lvl, j, sm, &s_old);
            gen++;
            grid_sync2(gen);
        }
    }

    // persist generation base for the next (graph-replayed) launch
    if (bid == 0 && tid == 0) g_gen_base = gen;
}

// ---------------------------------------------------------------------------
// K5: mean over T, decoder, log_softmax, new_hidden.
// ---------------------------------------------------------------------------
__global__ void final_kernel(const float* __restrict__ masks,
                             const float* __restrict__ decW,
                             const float* __restrict__ decb,
                             float* __restrict__ out) {
    int b = blockIdx.x;
    int tid = threadIdx.x;
    __shared__ float sout[DD];
    __shared__ float lg[NCC];
    __shared__ float lse;

    float mask_last = masks[b * TT + TT - 1];
    for (int d = tid; d < DD; d += blockDim.x) {
        float ms = 0.f;
        #pragma unroll
        for (int j = 1; j <= 8; j++) ms += g_state[j][b * SD + d];
        ms *= 0.125f;
        float last_raw = ms * mask_last;
        float acc = last_raw;
        for (int t = 0; t < TT - 1; t++)
            acc += g_hiddens[(size_t)t * BB * DD + b * DD + d] * masks[b * TT + t];
        sout[d] = acc * (1.f / TT);
        out[NCC * BB + b * DD + d] = last_raw;
    }
    __syncthreads();

    for (int c = tid; c < NCC; c += blockDim.x) {
        float acc = decb[c];
        const float* w = decW + (size_t)c * DD;
        for (int d = 0; d < DD; d++) acc = fmaf(sout[d], w[d], acc);
        lg[c] = acc;
    }
    __syncthreads();

    if (tid == 0) {
        float mx = lg[0];
        for (int c = 1; c < NCC; c++) mx = fmaxf(mx, lg[c]);
        float s = 0.f;
        for (int c = 0; c < NCC; c++) s += expf(lg[c] - mx);
        lse = mx + logf(s);
    }
    __syncthreads();

    for (int c = tid; c < NCC; c += blockDim.x)
        out[b * NCC + c] = lg[c] - lse;
}

// ---------------------------------------------------------------------------
// Host launcher
// ---------------------------------------------------------------------------
extern "C" void kernel_launch(void* const* d_in, const int* in_sizes, int n_in,
                              void* d_out, int out_size) {
    const int*   tokens = (const int*)  d_in[0];
    const float* masks  = (const float*)d_in[1];
    const int*   pos    = (const int*)  d_in[2];
    const int*   ner    = (const int*)  d_in[3];
    const float* hidden = (const float*)d_in[4];
    const float* encW   = (const float*)d_in[5];
    const float* nerW   = (const float*)d_in[6];
    const float* posW   = (const float*)d_in[7];
    const float* aggW   = (const float*)d_in[8];
    const float* aggb   = (const float*)d_in[9];
    const float* W0     = (const float*)d_in[10];
    const float* Ws     = (const float*)d_in[11];
    const float* decW   = (const float*)d_in[12];
    const float* decb   = (const float*)d_in[13];
    float* out = (float*)d_out;

    static int s_grid = 0;
    if (s_grid == 0) {
        int dev = 0;
        cudaGetDevice(&dev);
        cudaDeviceProp prop;
        cudaGetDeviceProperties(&prop, dev);
        s_grid = 2 * prop.multiProcessorCount;   // 2 CTAs/SM via launch_bounds(256,2)
        if (s_grid > MAXG) s_grid = MAXG;
    }

    float* p_combined;
    cudaGetSymbolAddress((void**)&p_combined, g_combined);

    // 1) gather embeddings + pack weights (independent)
    gather_kernel<<<TT * BB, 128>>>(tokens, ner, pos, encW, nerW, posW);
    pack_w<<<WMATS * NKT * NTILE, 128>>>(W0, Ws);

    // 2) agg linear -> x fragments   [8192, 850]
    {
        dim3 g((DD + 63) / 64, (TT * BB) / 64);
        gemm_agg_split<<<g, 256>>>(p_combined, aggW, aggb,
                                   TT * BB, DD, CIN, CIN, CIN);
    }
    // 3) xw0 = x @ W0top via fragment mma   [8192, 1700]
    xw0_mma<<<dim3(NTILE, (TT * BB) / 32), 256>>>();

    // 4) whole recurrence in ONE persistent kernel
    recur_persist<<<s_grid, 256>>>(hidden);

    // 5) mean over T, decoder, log_softmax, new_hidden
    final_kernel<<<BB, 256>>>(masks, decW, decb, out);
}

// round 17
// speedup vs baseline: 2.1636x; 1.0013x over previous
#include <cuda_runtime.h>
#include <cuda_bf16.h>
#include <math.h>
#include <stdint.h>

#define BB   64
#define TT   128
#define DD   850
#define D2   1700
#define CIN  910
#define NCC  42
#define NNER 30
#define NPOS 30
#define SD   864          // padded k stride; pads stay zero
#define NTILE 54          // 16-col pair tiles
#define NKT  54           // k16 tiles
#define WMATS 10          // 0..8 recurrent (W0bot, Ws[0..7]); 9 = W0top
#define XSTRIPS (TT * BB / 16)   // 512 row-strips of x
#define MAXG 512

// Scratch (device globals zero-initialized; pad regions never written)
__device__ float g_combined[TT * BB * CIN];
__device__ float g_xw0[TT * BB * D2];
__device__ float g_hiddens[TT * BB * DD];
__device__ float g_state[9][BB * SD];
__device__ float g_hprev[BB * SD];
__device__ int   g_tcnt[108];          // fold counters: mh*54 + tile
__device__ unsigned g_flags[MAXG];     // per-CTA arrival generation
__device__ volatile unsigned g_bcast;  // broadcast generation
__device__ unsigned g_gen_base;        // persistent across launches
// W fragments (2-way split): idx = ((wmat*NKT+kt)*NTILE+tile)*4 + ns, per lane.
__device__ __align__(256) uint4 g_Wf4[WMATS * NKT * NTILE * 4 * 32];
// A fragments (states 0..8, hprev=9), mma-A layout:
// uint4 per lane = {j0,j1,j2,j3}; idx = ((src*4+strip)*NKT+kt)*2 + term, x32 lanes
__device__ __align__(256) uint4 g_af4[10 * 4 * NKT * 2 * 32];
// x fragments for xw0 mma: idx = ((strip*NKT+kt)*2 + term) x32 lanes
__device__ __align__(256) uint4 g_xf4[(size_t)XSTRIPS * NKT * 2 * 32];

struct StepInfo { int wmat; int pred; int act; };
// act: 0 tanh, 1 relu, 2 sigmoid, 3 identity
__constant__ StepInfo c_steps[9] = {
    {0, -1, 0}, {1, 0, 2}, {2, 1, 1}, {3, 1, 1}, {4, 1, 3},
    {5, 2, 0}, {6, 5, 2}, {7, 3, 0}, {8, 5, 1},
};
// Levels: {s0},{s1},{s2,s3,s4},{s5,s7},{s6,s8}
__constant__ int c_nm[5]     = {1, 1, 3, 2, 2};
__constant__ int c_sid[5][3] = {{0,0,0},{1,1,1},{2,3,4},{5,7,7},{6,8,8}};

// Flag-array grid barrier, generation-based (equality compare: wrap-safe).
__device__ __forceinline__ void grid_sync2(unsigned gen) {
    __syncthreads();
    if (blockIdx.x == 0) {
        for (int i = 1 + threadIdx.x; i < (int)gridDim.x; i += blockDim.x) {
            while (((volatile unsigned*)g_flags)[i] != gen) { __nanosleep(32); }
        }
        __syncthreads();
        if (threadIdx.x == 0) {
            __threadfence();
            g_bcast = gen;
        }
        __syncthreads();
    } else {
        if (threadIdx.x == 0) {
            __threadfence();
            ((volatile unsigned*)g_flags)[blockIdx.x] = gen;
            while (g_bcast != gen) { __nanosleep(32); }
            __threadfence();
        }
        __syncthreads();
    }
}

// 2-way bf16 split of a value pair -> 2 packed bf16x2 words (x low, y high).
__device__ __forceinline__ void split2_pair(float x, float y,
        uint32_t& u1, uint32_t& u2) {
    __nv_bfloat162 b1 = __floats2bfloat162_rn(x, y);
    float rx = x - __bfloat162float(__low2bfloat16(b1));
    float ry = y - __bfloat162float(__high2bfloat16(b1));
    __nv_bfloat162 b2 = __floats2bfloat162_rn(rx, ry);
    u1 = *(uint32_t*)&b1; u2 = *(uint32_t*)&b2;
}

// Write a packed pair (value cols 2q,2q+1 of row m within a 64-row block,
// k-tile kt) into fragment layout at fragment-array word address space.
__device__ __forceinline__ void frag_write(uint32_t* base_words, int strips_nkt_off,
        int m, int q, int kt, uint32_t u1, uint32_t u2) {
    int r_ = m & 15;
    int strip = m >> 4;
    int j = ((r_ >= 8) ? 1 : 0) + ((q >= 4) ? 2 : 0);
    int lanep = (r_ & 7) * 4 + (q & 3);
    size_t i4 = (((size_t)(strips_nkt_off + strip) * NKT + kt) * 2) * 32 + lanep;
    base_words[i4 * 4 + j] = u1;
    base_words[(i4 + 32) * 4 + j] = u2;
}

__device__ __forceinline__ void mma_bf16(float* c, const uint32_t* a,
                                         uint32_t b0, uint32_t b1) {
    asm volatile(
        "mma.sync.aligned.m16n8k16.row.col.f32.bf16.bf16.f32 "
        "{%0,%1,%2,%3}, {%4,%5,%6,%7}, {%8,%9}, {%0,%1,%2,%3};"
        : "+f"(c[0]), "+f"(c[1]), "+f"(c[2]), "+f"(c[3])
        : "r"(a[0]), "r"(a[1]), "r"(a[2]), "r"(a[3]), "r"(b0), "r"(b1));
}

// Warp-owned-kt mainloop: for kt in [ktb,kte), load 4 unique A + 4 unique W
// uint4s and do all 24 mma. acc[strip][ng][nt][4].
__device__ __forceinline__ void kq_mainloop(
    float acc[2][2][2][4], const uint4* __restrict__ A0,
    const uint4* __restrict__ A1, const uint4* __restrict__ Wb,
    int ktb, int kte)
{
    #pragma unroll 2
    for (int kt = ktb; kt < kte; ++kt) {
        const uint4* wk = Wb + (size_t)kt * (NTILE * 128);
        uint4 w00 = wk[0];
        uint4 w01 = wk[32];
        uint4 w10 = wk[64];
        uint4 w11 = wk[96];
        #pragma unroll
        for (int s = 0; s < 2; ++s) {
            const uint4* Ab = s ? A1 : A0;
            uint4 At1 = Ab[(size_t)kt * 64];
            uint4 At2 = Ab[(size_t)kt * 64 + 32];
            uint32_t a1[4] = {At1.x, At1.y, At1.z, At1.w};
            uint32_t a2[4] = {At2.x, At2.y, At2.z, At2.w};
            mma_bf16(acc[s][0][0], a1, w00.x, w00.y);
            mma_bf16(acc[s][0][0], a1, w00.z, w00.w);
            mma_bf16(acc[s][0][0], a2, w00.x, w00.y);
            mma_bf16(acc[s][0][1], a1, w01.x, w01.y);
            mma_bf16(acc[s][0][1], a1, w01.z, w01.w);
            mma_bf16(acc[s][0][1], a2, w01.x, w01.y);
            mma_bf16(acc[s][1][0], a1, w10.x, w10.y);
            mma_bf16(acc[s][1][0], a1, w10.z, w10.w);
            mma_bf16(acc[s][1][0], a2, w10.x, w10.y);
            mma_bf16(acc[s][1][1], a1, w11.x, w11.y);
            mma_bf16(acc[s][1][1], a1, w11.z, w11.w);
            mma_bf16(acc[s][1][1], a2, w11.x, w11.y);
        }
    }
}

// Store a warp's 32x32 partial tile to sm[kq].
__device__ __forceinline__ void store_partial(
    float (*sm)[32][33], int kq, int lane, float acc[2][2][2][4])
{
    const int rl0 = lane >> 2;
    const int cb = (lane & 3) * 2;
    #pragma unroll
    for (int s = 0; s < 2; ++s)
    #pragma unroll
    for (int ng = 0; ng < 2; ++ng)
    #pragma unroll
    for (int nt = 0; nt < 2; ++nt) {
        const float* c = acc[s][ng][nt];
        int row = s * 16 + rl0;
        int col = ng * 16 + nt * 8 + cb;
        sm[kq][row][col]         = c[0];
        sm[kq][row][col + 1]     = c[1];
        sm[kq][row + 8][col]     = c[2];
        sm[kq][row + 8][col + 1] = c[3];
    }
}

// ---------------------------------------------------------------------------
// K1: gather embeddings
// ---------------------------------------------------------------------------
__global__ void gather_kernel(const int* __restrict__ tokens,
                              const int* __restrict__ ner,
                              const int* __restrict__ pos,
                              const float* __restrict__ encW,
                              const float* __restrict__ nerW,
                              const float* __restrict__ posW) {
    int r = blockIdx.x;
    int b = r & (BB - 1);
    int t = r >> 6;
    int tok = tokens[b * TT + t];
    int nid = ner[b * TT + t];
    int pid = pos[b * TT + t];
    float* dst = g_combined + (size_t)r * CIN;
    for (int c = threadIdx.x; c < CIN; c += blockDim.x) {
        float v;
        if (c < DD)             v = encW[(size_t)tok * DD + c];
        else if (c < DD + NNER) v = nerW[nid * NNER + (c - DD)];
        else                    v = posW[pid * NPOS + (c - DD - NNER)];
        dst[c] = v;
    }
}

// ---------------------------------------------------------------------------
// K2: agg GEMM: x = combined @ aggW^T + aggb, epilogue writes x FRAGMENTS.
// ---------------------------------------------------------------------------
__global__ void gemm_agg_split(const float* __restrict__ A, const float* __restrict__ Bm,
                               const float* __restrict__ bias,
                               int M, int N, int K, int lda, int ldb) {
    __shared__ __align__(16) float As[16 * 64];
    __shared__ __align__(16) float Bs[16 * 64];
    int tid = threadIdx.x;
    int m0 = blockIdx.y * 64;
    int n0 = blockIdx.x * 64;
    int mi = tid & 15;
    int ni = tid >> 4;
    float acc[4][4] = {};

    for (int k0 = 0; k0 < K; k0 += 16) {
        __syncthreads();
        #pragma unroll
        for (int i = 0; i < 4; i++) {
            int e = tid + 256 * i;
            int m = e >> 4, k = e & 15;
            int kk = k0 + k;
            float v = 0.f;
            if (kk < K) v = A[(size_t)(m0 + m) * lda + kk];
            As[k * 64 + m] = v;
        }
        #pragma unroll
        for (int i = 0; i < 4; i++) {
            int e = tid + 256 * i;
            int n = e >> 4, k = e & 15;
            int kk = k0 + k, nn = n0 + n;
            float v = 0.f;
            if (kk < K && nn < N) v = Bm[(size_t)nn * ldb + kk];
            Bs[k * 64 + n] = v;
        }
        __syncthreads();
        #pragma unroll
        for (int k = 0; k < 16; k++) {
            float4 a4 = *(const float4*)(As + k * 64 + mi * 4);
            float4 b4 = *(const float4*)(Bs + k * 64 + ni * 4);
            acc[0][0] = fmaf(a4.x, b4.x, acc[0][0]);
            acc[0][1] = fmaf(a4.x, b4.y, acc[0][1]);
            acc[0][2] = fmaf(a4.x, b4.z, acc[0][2]);
            acc[0][3] = fmaf(a4.x, b4.w, acc[0][3]);
            acc[1][0] = fmaf(a4.y, b4.x, acc[1][0]);
            acc[1][1] = fmaf(a4.y, b4.y, acc[1][1]);
            acc[1][2] = fmaf(a4.y, b4.z, acc[1][2]);
            acc[1][3] = fmaf(a4.y, b4.w, acc[1][3]);
            acc[2][0] = fmaf(a4.z, b4.x, acc[2][0]);
            acc[2][1] = fmaf(a4.z, b4.y, acc[2][1]);
            acc[2][2] = fmaf(a4.z, b4.z, acc[2][2]);
            acc[2][3] = fmaf(a4.z, b4.w, acc[2][3]);
            acc[3][0] = fmaf(a4.w, b4.x, acc[3][0]);
            acc[3][1] = fmaf(a4.w, b4.y, acc[3][1]);
            acc[3][2] = fmaf(a4.w, b4.z, acc[3][2]);
            acc[3][3] = fmaf(a4.w, b4.w, acc[3][3]);
        }
    }
    #pragma unroll
    for (int r = 0; r < 4; r++) {
        int mm = m0 + mi * 4 + r;
        int nn0 = n0 + ni * 4;
        #pragma unroll
        for (int pr = 0; pr < 2; pr++) {
            int nn = nn0 + 2 * pr;
            if (nn < N) {
                float v0 = acc[r][2 * pr]     + bias[nn];
                float v1 = acc[r][2 * pr + 1] + bias[nn + 1];
                uint32_t u1, u2;
                split2_pair(v0, v1, u1, u2);
                frag_write((uint32_t*)g_xf4, 0, mm, (nn >> 1) & 7, nn >> 4, u1, u2);
            }
        }
    }
}

// ---------------------------------------------------------------------------
// K3: pack weights into 2-term bf16 mma-fragment layout (10 matrices).
// ---------------------------------------------------------------------------
__global__ void pack_w(const float* __restrict__ W0, const float* __restrict__ Ws) {
    int id = blockIdx.x;
    int pt = id % NTILE;
    int kt = (id / NTILE) % NKT;
    int mat = id / (NTILE * NKT);
    int ns = threadIdx.x >> 5;
    int lane = threadIdx.x & 31;
    const float* W = (mat == 0) ? (W0 + (size_t)DD * D2)
                   : (mat == 9) ? W0
                                : (Ws + (size_t)(mat - 1) * DD * D2);
    int half = ns >> 1;
    int col = pt * 16 + (ns & 1) * 8 + (lane >> 2);
    int gcol = (col < DD) ? (half ? DD + col : col) : -1;
    int k0 = kt * 16 + (lane & 3) * 2;
    float v[4];
    #pragma unroll
    for (int j = 0; j < 4; ++j) {
        int k = k0 + (j & 1) + (j >> 1) * 8;
        v[j] = (gcol >= 0 && k < DD) ? W[(size_t)k * D2 + gcol] : 0.f;
    }
    uint32_t a1, a2, b1, b2;
    split2_pair(v[0], v[1], a1, a2);
    split2_pair(v[2], v[3], b1, b2);
    g_Wf4[((size_t)id * 4 + ns) * 32 + lane] = make_uint4(a1, b1, a2, b2);
}

// ---------------------------------------------------------------------------
// K4: xw0 = x @ W0top, warp-owned-kt mainloop. grid = (54 tiles, 256 mb).
// ---------------------------------------------------------------------------
__global__ __launch_bounds__(256)
void xw0_mma() {
    __shared__ float sm[8][32][33];
    const int tile = blockIdx.x;
    const int mb = blockIdx.y;
    const int tid = threadIdx.x;
    const int lane = tid & 31;
    const int kq = tid >> 5;

    const int ktb = (NKT * kq) >> 3;
    const int kte = (NKT * (kq + 1)) >> 3;

    const uint4* __restrict__ A0 = g_xf4 + ((size_t)(mb * 2 + 0) * NKT) * 64 + lane;
    const uint4* __restrict__ A1 = g_xf4 + ((size_t)(mb * 2 + 1) * NKT) * 64 + lane;
    const uint4* __restrict__ Wb =
        g_Wf4 + ((size_t)(9 * NKT) * NTILE) * 128 + (size_t)tile * 128 + lane;

    float acc[2][2][2][4] = {};
    kq_mainloop(acc, A0, A1, Wb, ktb, kte);
    store_partial(sm, kq, lane, acc);
    __syncthreads();

    const int ml = tid >> 3;
    const int q = tid & 7;
    const int p0 = tile * 16 + 2 * q;
    const int row = mb * 32 + ml;
    if (p0 < DD) {
        float cc0 = 0.f, cc1 = 0.f, hh0 = 0.f, hh1 = 0.f;
        #pragma unroll
        for (int k8 = 0; k8 < 8; ++k8) {
            cc0 += sm[k8][ml][2 * q];
            cc1 += sm[k8][ml][2 * q + 1];
            hh0 += sm[k8][ml][16 + 2 * q];
            hh1 += sm[k8][ml][16 + 2 * q + 1];
        }
        float* xw = g_xw0 + (size_t)row * D2;
        __stcs((float2*)&xw[p0],      make_float2(cc0, cc1));
        __stcs((float2*)&xw[DD + p0], make_float2(hh0, hh1));
    }
}

// ---------------------------------------------------------------------------
// One recurrence job: C[32 rows x (16c+16h)] full-K.
// 8 warps own k-ranges; partials combined via smem in fixed kq order.
// Level 4 jobs additionally fold next-step prep via per-(mh,tile) counter.
// ---------------------------------------------------------------------------
__device__ __forceinline__ void do_job(
    int t, int lvl, int j, float (*sm)[32][33], int* s_old)
{
    const int tile = j % NTILE;
    const int r = j / NTILE;
    const int mh = r & 1;
    const int mi = r >> 1;
    const int sid = c_sid[lvl][mi];
    const StepInfo si = c_steps[sid];
    const int asrc = (si.pred < 0) ? 9 : si.pred;
    const float* __restrict__ Afp = (si.pred < 0) ? g_hprev : g_state[si.pred];

    const int tid = threadIdx.x;
    const int lane = tid & 31;
    const int kq = tid >> 5;

    const int ktb = (NKT * kq) >> 3;
    const int kte = (NKT * (kq + 1)) >> 3;

    const uint4* __restrict__ A0 =
        g_af4 + ((size_t)(asrc * 4 + mh * 2 + 0) * NKT) * 64 + lane;
    const uint4* __restrict__ A1 =
        g_af4 + ((size_t)(asrc * 4 + mh * 2 + 1) * NKT) * 64 + lane;
    const uint4* __restrict__ Wb =
        g_Wf4 + ((size_t)(si.wmat * NKT) * NTILE) * 128 + (size_t)tile * 128 + lane;

    float acc[2][2][2][4] = {};
    kq_mainloop(acc, A0, A1, Wb, ktb, kte);
    store_partial(sm, kq, lane, acc);
    __syncthreads();

    // epilogue: 256 threads = 32 rows x 8 col-pairs
    const int ml = tid >> 3;
    const int q = tid & 7;
    const int p0 = tile * 16 + 2 * q;
    const int m = mh * 32 + ml;
    if (p0 < DD) {
        float vv[2];
        #pragma unroll
        for (int e = 0; e < 2; ++e) {
            int cp = 2 * q + e;
            int p = p0 + e;
            float cc = 0.f, hh = 0.f;
            #pragma unroll
            for (int k8 = 0; k8 < 8; ++k8) {
                cc += sm[k8][ml][cp];
                hh += sm[k8][ml][16 + cp];
            }
            if (si.pred < 0) {
                const float* xw = g_xw0 + ((size_t)t * BB + m) * D2;
                cc += __ldcs(xw + p);
                hh += __ldcs(xw + DD + p);
            }
            float sp = Afp[(size_t)m * SD + p];
            float g = 1.f / (1.f + expf(-cc));
            float av = (si.act == 0) ? tanhf(hh)
                     : (si.act == 1) ? fmaxf(hh, 0.f)
                     : (si.act == 2) ? 1.f / (1.f + expf(-hh)) : hh;
            vv[e] = sp + g * (av - sp);
        }
        *(float2*)&g_state[sid][(size_t)m * SD + p0] = make_float2(vv[0], vv[1]);
        uint32_t u1, u2;
        split2_pair(vv[0], vv[1], u1, u2);
        frag_write((uint32_t*)g_af4, sid * 4, m, q, tile, u1, u2);
    }
    __syncthreads();   // smem reusable by next job

    // level-4 fold: when both mats (6,8) of this (mh,tile) block are done,
    // compute next-step hprev (+ hiddens[t]) for these rows/cols.
    if (lvl == 4) {
        __threadfence();
        __syncthreads();
        if (tid == 0) *s_old = atomicAdd(&g_tcnt[mh * 54 + tile], 1);
        __syncthreads();
        if (*s_old == 1) {
            __threadfence();
            if (p0 < DD) {
                float v0 = 0.f, v1 = 0.f;
                #pragma unroll
                for (int jj = 1; jj <= 8; ++jj) {
                    v0 += g_state[jj][(size_t)m * SD + p0];
                    v1 += g_state[jj][(size_t)m * SD + p0 + 1];
                }
                v0 *= 0.125f;
                v1 *= 0.125f;
                *(float2*)&g_hprev[(size_t)m * SD + p0] = make_float2(v0, v1);
                *(float2*)&g_hiddens[(size_t)t * BB * DD + (size_t)m * DD + p0]
                    = make_float2(v0, v1);
                uint32_t u1, u2;
                split2_pair(v0, v1, u1, u2);
                frag_write((uint32_t*)g_af4, 9 * 4, m, q, tile, u1, u2);
            }
            __syncthreads();
            if (tid == 0) g_tcnt[mh * 54 + tile] = 0;
        }
        __syncthreads();
    }
}

__global__ __launch_bounds__(256, 2)
void recur_persist(const float* __restrict__ hidden) {
    __shared__ float sm[8][32][33];
    __shared__ int s_old;
    const int bid = blockIdx.x;
    const int G = gridDim.x;
    const int tid = threadIdx.x;

    unsigned gen = g_gen_base;

    // initial prep (t = 0): hprev = hidden, plus fragment splits
    for (int i = bid * 256 + tid; i < BB * 425; i += G * 256) {
        int m = i / 425;
        int qd = i - m * 425;
        int d0 = 2 * qd;
        float v0 = hidden[m * DD + d0];
        float v1 = hidden[m * DD + d0 + 1];
        *(float2*)&g_hprev[(size_t)m * SD + d0] = make_float2(v0, v1);
        uint32_t u1, u2;
        split2_pair(v0, v1, u1, u2);
        frag_write((uint32_t*)g_af4, 9 * 4, m, qd & 7, d0 >> 4, u1, u2);
    }
    gen++;
    grid_sync2(gen);

    for (int t = 0; t < TT; ++t) {
        #pragma unroll
        for (int lvl = 0; lvl < 5; ++lvl) {
            const int jobs = c_nm[lvl] * 108;
            for (int j = bid; j < jobs; j += G)
                do_job(t, lvl, j, sm, &s_old);
            gen++;
            grid_sync2(gen);
        }
    }

    if (bid == 0 && tid == 0) g_gen_base = gen;
}

// ---------------------------------------------------------------------------
// K5: mean over T, decoder, log_softmax, new_hidden.
// ---------------------------------------------------------------------------
__global__ void final_kernel(const float* __restrict__ masks,
                             const float* __restrict__ decW,
                             const float* __restrict__ decb,
                             float* __restrict__ out) {
    int b = blockIdx.x;
    int tid = threadIdx.x;
    __shared__ float sout[DD];
    __shared__ float lg[NCC];
    __shared__ float lse;

    float mask_last = masks[b * TT + TT - 1];
    for (int d = tid; d < DD; d += blockDim.x) {
        float ms = 0.f;
        #pragma unroll
        for (int j = 1; j <= 8; j++) ms += g_state[j][b * SD + d];
        ms *= 0.125f;
        float last_raw = ms * mask_last;
        float acc = last_raw;
        for (int t = 0; t < TT - 1; t++)
            acc += g_hiddens[(size_t)t * BB * DD + b * DD + d] * masks[b * TT + t];
        sout[d] = acc * (1.f / TT);
        out[NCC * BB + b * DD + d] = last_raw;
    }
    __syncthreads();

    for (int c = tid; c < NCC; c += blockDim.x) {
        float acc = decb[c];
        const float* w = decW + (size_t)c * DD;
        for (int d = 0; d < DD; d++) acc = fmaf(sout[d], w[d], acc);
        lg[c] = acc;
    }
    __syncthreads();

    if (tid == 0) {
        float mx = lg[0];
        for (int c = 1; c < NCC; c++) mx = fmaxf(mx, lg[c]);
        float s = 0.f;
        for (int c = 0; c < NCC; c++) s += expf(lg[c] - mx);
        lse = mx + logf(s);
    }
    __syncthreads();

    for (int c = tid; c < NCC; c += blockDim.x)
        out[b * NCC + c] = lg[c] - lse;
}

// ---------------------------------------------------------------------------
// Host launcher
// ---------------------------------------------------------------------------
extern "C" void kernel_launch(void* const* d_in, const int* in_sizes, int n_in,
                              void* d_out, int out_size) {
    const int*   tokens = (const int*)  d_in[0];
    const float* masks  = (const float*)d_in[1];
    const int*   pos    = (const int*)  d_in[2];
    const int*   ner    = (const int*)  d_in[3];
    const float* hidden = (const float*)d_in[4];
    const float* encW   = (const float*)d_in[5];
    const float* nerW   = (const float*)d_in[6];
    const float* posW   = (const float*)d_in[7];
    const float* aggW   = (const float*)d_in[8];
    const float* aggb   = (const float*)d_in[9];
    const float* W0     = (const float*)d_in[10];
    const float* Ws     = (const float*)d_in[11];
    const float* decW   = (const float*)d_in[12];
    const float* decb   = (const float*)d_in[13];
    float* out = (float*)d_out;

    static int s_grid = 0;
    if (s_grid == 0) {
        int dev = 0;
        cudaGetDevice(&dev);
        cudaDeviceProp prop;
        cudaGetDeviceProperties(&prop, dev);
        s_grid = 2 * prop.multiProcessorCount;
        if (s_grid > MAXG) s_grid = MAXG;
    }

    float* p_combined;
    cudaGetSymbolAddress((void**)&p_combined, g_combined);

    // 1) gather embeddings + pack weights (independent)
    gather_kernel<<<TT * BB, 128>>>(tokens, ner, pos, encW, nerW, posW);
    pack_w<<<WMATS * NKT * NTILE, 128>>>(W0, Ws);

    // 2) agg linear -> x fragments   [8192, 850]
    {
        dim3 g((DD + 63) / 64, (TT * BB) / 64);
        gemm_agg_split<<<g, 256>>>(p_combined, aggW, aggb,
                                   TT * BB, DD, CIN, CIN, CIN);
    }
    // 3) xw0 = x @ W0top via fragment mma   [8192, 1700]
    xw0_mma<<<dim3(NTILE, (TT * BB) / 32), 256>>>();

    // 4) whole recurrence in ONE persistent kernel
    recur_persist<<<s_grid, 256>>>(hidden);

    // 5) mean over T, decoder, log_softmax, new_hidden
    final_kernel<<<BB, 256>>>(masks, decW, decb, out);
}